// round 1
// baseline (speedup 1.0000x reference)
#include <cuda_runtime.h>
#include <cuda_bf16.h>
#include <math.h>

#define N_ENT    100000
#define N_REL    16
#define DIM      128
#define N_BASES  4
#define N_EDGES  640000
#define BATCH    1024
#define N_NEG    64
#define NCOLS    640          // 128 self-loop + 4*128 basis projections
#define BN_EPS   1e-5f

// ---------------- device scratch (static: no allocation at runtime) -------
__device__ float g_x[N_ENT * DIM];        // current node features (51 MB)
__device__ float g_out[N_ENT * DIM];      // pre-BN accumulator     (51 MB)
__device__ float g_Y[N_ENT * 512];        // 4 basis projections    (205 MB)
__device__ float g_deg[N_ENT];
__device__ float g_Wcat[2 * DIM * NCOLS]; // per-layer [128 x 640] fused weight
__device__ float g_sum[DIM];
__device__ float g_sumsq[DIM];

// ---------------- f32x2 packed-FMA helpers (Blackwell) --------------------
__device__ __forceinline__ unsigned long long pack_dup(float a) {
    unsigned long long r;
    asm("mov.b64 %0, {%1, %1};" : "=l"(r) : "f"(a));
    return r;
}
__device__ __forceinline__ void fma2(unsigned long long& d,
                                     unsigned long long a,
                                     unsigned long long b) {
    asm("fma.rn.f32x2 %0, %1, %2, %0;" : "+l"(d) : "l"(a), "l"(b));
}
__device__ __forceinline__ float2 unpack2(unsigned long long v) {
    float2 r;
    asm("mov.b64 {%0, %1}, %2;" : "=f"(r.x), "=f"(r.y) : "l"(v));
    return r;
}

// ---------------- setup kernels -------------------------------------------
__global__ void k_copy_x(const float* __restrict__ ent) {
    int i = blockIdx.x * blockDim.x + threadIdx.x;       // float4 index
    int total = N_ENT * DIM / 4;
    if (i < total)
        reinterpret_cast<float4*>(g_x)[i] =
            reinterpret_cast<const float4*>(ent)[i];
}

__global__ void k_zero_deg() {
    int i = blockIdx.x * blockDim.x + threadIdx.x;
    if (i < N_ENT) g_deg[i] = 0.0f;
}

__global__ void k_deg(const int* __restrict__ ei) {
    int e = blockIdx.x * blockDim.x + threadIdx.x;
    if (e < N_EDGES) atomicAdd(&g_deg[ei[N_EDGES + e]], 1.0f);
}

// build Wcat[l] = [ w_sl[l] | bases[l][0] | bases[l][1] | bases[l][2] | bases[l][3] ]
__global__ void k_wcat(const float* __restrict__ w_sl,
                       const float* __restrict__ bases) {
    int idx = blockIdx.x * blockDim.x + threadIdx.x;
    int total = 2 * DIM * NCOLS;
    if (idx >= total) return;
    int l   = idx / (DIM * NCOLS);
    int rem = idx - l * (DIM * NCOLS);
    int d   = rem / NCOLS;
    int col = rem - d * NCOLS;
    float v;
    if (col < DIM) {
        v = w_sl[l * DIM * DIM + d * DIM + col];
    } else {
        int b = (col - DIM) >> 7;
        int f = (col - DIM) & 127;
        v = bases[l * N_BASES * DIM * DIM + b * DIM * DIM + d * DIM + f];
    }
    g_Wcat[l * DIM * NCOLS + d * NCOLS + col] = v;
}

__global__ void k_zero_stats() {
    int t = threadIdx.x;
    if (t < DIM) { g_sum[t] = 0.0f; g_sumsq[t] = 0.0f; }
}

// ---------------- fused GEMM: Z = x @ Wcat  (100000 x 128 @ 128 x 640) ----
// First 128 cols (+bias) -> g_out (self-loop), remaining 512 -> g_Y.
// 64x64 tile, 256 threads, 4x4 microtile, packed f32x2 FMA.
__global__ __launch_bounds__(256) void k_gemm(int layer,
                                              const float* __restrict__ b_sl) {
    __shared__ float xs[64][36];   // stride 36: conflict-free + 16B aligned
    __shared__ float ws[32][64];

    const float* __restrict__ W = g_Wcat + layer * DIM * NCOLS;
    const float* __restrict__ bias = b_sl + layer * DIM;

    int tid = threadIdx.x;
    int tx = tid & 15;
    int ty = tid >> 4;
    int m0 = blockIdx.x * 64;
    int n0 = blockIdx.y * 64;

    unsigned long long acc[4][2];
#pragma unroll
    for (int i = 0; i < 4; i++) { acc[i][0] = 0ull; acc[i][1] = 0ull; }

    for (int kc = 0; kc < DIM; kc += 32) {
        // load x tile: 64 rows x 32 cols = 512 float4
#pragma unroll
        for (int i = 0; i < 2; i++) {
            int lin = tid + i * 256;
            int row = lin >> 3;
            int q   = lin & 7;
            float4 v = make_float4(0.f, 0.f, 0.f, 0.f);
            if (m0 + row < N_ENT)
                v = *reinterpret_cast<const float4*>(
                        &g_x[(m0 + row) * DIM + kc + q * 4]);
            *reinterpret_cast<float4*>(&xs[row][q * 4]) = v;
        }
        // load W tile: 32 rows x 64 cols
#pragma unroll
        for (int i = 0; i < 2; i++) {
            int lin = tid + i * 256;
            int r = lin >> 4;
            int q = lin & 15;
            *reinterpret_cast<float4*>(&ws[r][q * 4]) =
                *reinterpret_cast<const float4*>(
                    &W[(kc + r) * NCOLS + n0 + q * 4]);
        }
        __syncthreads();
#pragma unroll
        for (int kk = 0; kk < 32; kk++) {
            ulonglong2 b2 = *reinterpret_cast<ulonglong2*>(&ws[kk][tx * 4]);
#pragma unroll
            for (int i = 0; i < 4; i++) {
                unsigned long long ap = pack_dup(xs[ty * 4 + i][kk]);
                fma2(acc[i][0], ap, b2.x);
                fma2(acc[i][1], ap, b2.y);
            }
        }
        __syncthreads();
    }

    int col = n0 + tx * 4;
    bool isOut = (col < DIM);
    float4 bv = make_float4(0.f, 0.f, 0.f, 0.f);
    if (isOut) bv = *reinterpret_cast<const float4*>(&bias[col]);
#pragma unroll
    for (int i = 0; i < 4; i++) {
        int m = m0 + ty * 4 + i;
        if (m >= N_ENT) continue;
        float2 p0 = unpack2(acc[i][0]);
        float2 p1 = unpack2(acc[i][1]);
        if (isOut) {
            float4 o = make_float4(p0.x + bv.x, p0.y + bv.y,
                                   p1.x + bv.z, p1.y + bv.w);
            *reinterpret_cast<float4*>(&g_out[m * DIM + col]) = o;
        } else {
            *reinterpret_cast<float4*>(&g_Y[m * 512 + (col - DIM)]) =
                make_float4(p0.x, p0.y, p1.x, p1.y);
        }
    }
}

// ---------------- edge kernel: one warp per edge --------------------------
// msg = sum_b coeff[type][b] * Y[src, b*128 .. b*128+127]; atomic add to out[dst]
__global__ __launch_bounds__(256) void k_edge(const int* __restrict__ ei,
                                              const int* __restrict__ et,
                                              const float* __restrict__ coeff) {
    int warp = (blockIdx.x * blockDim.x + threadIdx.x) >> 5;
    int lane = threadIdx.x & 31;
    if (warp >= N_EDGES) return;

    int s = ei[warp];
    int d = ei[N_EDGES + warp];
    int t = et[warp];

    float4 c = *reinterpret_cast<const float4*>(&coeff[t * 4]);
    const float4* yr =
        reinterpret_cast<const float4*>(&g_Y[s * 512]) + lane;  // +32 per basis
    float4 y0 = yr[0], y1 = yr[32], y2 = yr[64], y3 = yr[96];

    float4 m;
    m.x = c.x * y0.x + c.y * y1.x + c.z * y2.x + c.w * y3.x;
    m.y = c.x * y0.y + c.y * y1.y + c.z * y2.y + c.w * y3.y;
    m.z = c.x * y0.z + c.y * y1.z + c.z * y2.z + c.w * y3.z;
    m.w = c.x * y0.w + c.y * y1.w + c.z * y2.w + c.w * y3.w;

    atomicAdd(reinterpret_cast<float4*>(&g_out[d * DIM + lane * 4]), m);
}

// ---------------- BN pass 1: divide by deg (in place) + column sums -------
__global__ __launch_bounds__(128) void k_bn_stats() {
    int col = threadIdx.x;
    int r0 = blockIdx.x * 256;
    int r1 = r0 + 256; if (r1 > N_ENT) r1 = N_ENT;
    float s = 0.0f, q = 0.0f;
    for (int r = r0; r < r1; r++) {
        float invd = 1.0f / fmaxf(g_deg[r], 1.0f);
        float v = g_out[r * DIM + col] * invd;
        g_out[r * DIM + col] = v;
        s += v;
        q += v * v;
    }
    atomicAdd(&g_sum[col], s);
    atomicAdd(&g_sumsq[col], q);
}

// ---------------- BN pass 2: normalize + affine + relu -> g_x -------------
__global__ __launch_bounds__(256) void k_bn_apply(int layer,
                                                  const float* __restrict__ gamma,
                                                  const float* __restrict__ beta) {
    const float INV_N = 1.0f / (float)N_ENT;
    int i = blockIdx.x * blockDim.x + threadIdx.x;    // float4 index
    int total = N_ENT * DIM / 4;
    if (i >= total) return;
    int c0 = (i & 31) * 4;
    float4 v  = reinterpret_cast<const float4*>(g_out)[i];
    float4 s4 = *reinterpret_cast<const float4*>(&g_sum[c0]);
    float4 q4 = *reinterpret_cast<const float4*>(&g_sumsq[c0]);
    float4 gm = *reinterpret_cast<const float4*>(&gamma[layer * DIM + c0]);
    float4 bt = *reinterpret_cast<const float4*>(&beta[layer * DIM + c0]);

    float4 o;
    {
        float mu = s4.x * INV_N; float var = q4.x * INV_N - mu * mu;
        o.x = fmaxf((v.x - mu) * rsqrtf(var + BN_EPS) * gm.x + bt.x, 0.f);
    }
    {
        float mu = s4.y * INV_N; float var = q4.y * INV_N - mu * mu;
        o.y = fmaxf((v.y - mu) * rsqrtf(var + BN_EPS) * gm.y + bt.y, 0.f);
    }
    {
        float mu = s4.z * INV_N; float var = q4.z * INV_N - mu * mu;
        o.z = fmaxf((v.z - mu) * rsqrtf(var + BN_EPS) * gm.z + bt.z, 0.f);
    }
    {
        float mu = s4.w * INV_N; float var = q4.w * INV_N - mu * mu;
        o.w = fmaxf((v.w - mu) * rsqrtf(var + BN_EPS) * gm.w + bt.w, 0.f);
    }
    reinterpret_cast<float4*>(g_x)[i] = o;
}

// ---------------- scoring: TransE distances -------------------------------
__global__ __launch_bounds__(256) void k_score(const int* __restrict__ head,
                                               const int* __restrict__ relidx,
                                               const int* __restrict__ tail,
                                               const int* __restrict__ neg,
                                               const float* __restrict__ rel_tab,
                                               float* __restrict__ out) {
    __shared__ float hr[DIM];
    int b = blockIdx.x;
    int tid = threadIdx.x;
    int h = head[b], r = relidx[b], t = tail[b];
    if (tid < DIM)
        hr[tid] = g_x[h * DIM + tid] + rel_tab[r * DIM + tid];
    __syncthreads();

    int wid = tid >> 5, lane = tid & 31;
    const float4* h4 = reinterpret_cast<const float4*>(hr);
    float4 hv = h4[lane];

    for (int j = wid; j < 1 + N_NEG; j += 8) {
        int target = (j == 0) ? t : neg[b * N_NEG + (j - 1)];
        float4 ev = reinterpret_cast<const float4*>(&g_x[target * DIM])[lane];
        float dx = hv.x - ev.x, dy = hv.y - ev.y,
              dz = hv.z - ev.z, dw = hv.w - ev.w;
        float sum = dx * dx + dy * dy + dz * dz + dw * dw;
#pragma unroll
        for (int off = 16; off > 0; off >>= 1)
            sum += __shfl_xor_sync(0xffffffffu, sum, off);
        if (lane == 0) {
            float sc = -sqrtf(sum);
            if (j == 0) out[b] = sc;
            else        out[BATCH + b * N_NEG + (j - 1)] = sc;
        }
    }
}

// ---------------- launcher ------------------------------------------------
extern "C" void kernel_launch(void* const* d_in, const int* in_sizes, int n_in,
                              void* d_out, int out_size) {
    const int*   head    = (const int*)d_in[0];
    const int*   relidx  = (const int*)d_in[1];
    const int*   tail    = (const int*)d_in[2];
    const int*   neg     = (const int*)d_in[3];
    const int*   ei      = (const int*)d_in[4];
    const int*   et      = (const int*)d_in[5];
    const float* ent_tab = (const float*)d_in[6];
    const float* rel_tab = (const float*)d_in[7];
    const float* bases   = (const float*)d_in[8];
    const float* coeffs  = (const float*)d_in[9];
    const float* w_sl    = (const float*)d_in[10];
    const float* b_sl    = (const float*)d_in[11];
    const float* gamma   = (const float*)d_in[12];
    const float* beta    = (const float*)d_in[13];
    float* out = (float*)d_out;

    // setup
    k_copy_x<<<(N_ENT * DIM / 4 + 255) / 256, 256>>>(ent_tab);
    k_zero_deg<<<(N_ENT + 255) / 256, 256>>>();
    k_deg<<<(N_EDGES + 255) / 256, 256>>>(ei);
    k_wcat<<<(2 * DIM * NCOLS + 255) / 256, 256>>>(w_sl, bases);

    dim3 ggrid((N_ENT + 63) / 64, NCOLS / 64);
    for (int l = 0; l < 2; l++) {
        k_gemm<<<ggrid, 256>>>(l, b_sl);
        k_edge<<<(N_EDGES * 32 + 255) / 256, 256>>>(ei, et, coeffs + l * N_REL * N_BASES);
        k_zero_stats<<<1, 128>>>();
        k_bn_stats<<<(N_ENT + 255) / 256, 128>>>();
        k_bn_apply<<<(N_ENT * DIM / 4 + 255) / 256, 256>>>(l, gamma, beta);
    }

    k_score<<<BATCH, 256>>>(head, relidx, tail, neg, rel_tab, out);
}

// round 2
// speedup vs baseline: 1.2462x; 1.2462x over previous
#include <cuda_runtime.h>
#include <cuda_bf16.h>
#include <math.h>

#define N_ENT    100000
#define N_REL    16
#define DIM      128
#define N_BASES  4
#define N_EDGES  640000
#define BATCH    1024
#define N_NEG    64
#define NCOLS    640          // 128 self-loop + 4*128 basis projections
#define BN_EPS   1e-5f

// ---------------- device scratch (static: no allocation at runtime) -------
__device__ float g_x[N_ENT * DIM];        // current node features (51 MB)
__device__ float g_out[N_ENT * DIM];      // pre-BN accumulator     (51 MB)
__device__ float g_Y[N_ENT * 512];        // 4 basis projections    (205 MB)
__device__ float g_deg[N_ENT];
__device__ float g_sum[DIM];
__device__ float g_sumsq[DIM];
// W split into bf16 hi/lo, k-pair-interleaved for direct B-fragment loads:
// u32 index (l, k2, n) -> packs { W[2*k2][n], W[2*k2+1][n] } as 2x bf16
__device__ __nv_bfloat16 g_Wh[2 * 64 * NCOLS * 2];
__device__ __nv_bfloat16 g_Wl[2 * 64 * NCOLS * 2];

// ---------------- setup kernels -------------------------------------------
__global__ void k_copy_x(const float* __restrict__ ent) {
    int i = blockIdx.x * blockDim.x + threadIdx.x;       // float4 index
    int total = N_ENT * DIM / 4;
    if (i < total)
        reinterpret_cast<float4*>(g_x)[i] =
            reinterpret_cast<const float4*>(ent)[i];
}

__global__ void k_zero_deg() {
    int i = blockIdx.x * blockDim.x + threadIdx.x;
    if (i < N_ENT) g_deg[i] = 0.0f;
}

__global__ void k_deg(const int* __restrict__ ei) {
    int e = blockIdx.x * blockDim.x + threadIdx.x;
    if (e < N_EDGES) atomicAdd(&g_deg[ei[N_EDGES + e]], 1.0f);
}

// build fused weight [w_sl | B0 | B1 | B2 | B3], split to bf16 hi/lo,
// store k-pair-interleaved: bf16 index = ((l*64 + k/2)*NCOLS + n)*2 + (k&1)
__global__ void k_wcat(const float* __restrict__ w_sl,
                       const float* __restrict__ bases) {
    int idx = blockIdx.x * blockDim.x + threadIdx.x;
    int total = 2 * DIM * NCOLS;
    if (idx >= total) return;
    int l   = idx / (DIM * NCOLS);
    int rem = idx - l * (DIM * NCOLS);
    int k   = rem / NCOLS;
    int n   = rem - k * NCOLS;
    float v;
    if (n < DIM) {
        v = w_sl[l * DIM * DIM + k * DIM + n];
    } else {
        int b = (n - DIM) >> 7;
        int f = (n - DIM) & 127;
        v = bases[l * N_BASES * DIM * DIM + b * DIM * DIM + k * DIM + f];
    }
    __nv_bfloat16 hi = __float2bfloat16(v);
    __nv_bfloat16 lo = __float2bfloat16(v - __bfloat162float(hi));
    int dst = ((l * 64 + (k >> 1)) * NCOLS + n) * 2 + (k & 1);
    g_Wh[dst] = hi;
    g_Wl[dst] = lo;
}

__global__ void k_zero_stats() {
    int t = threadIdx.x;
    if (t < DIM) { g_sum[t] = 0.0f; g_sumsq[t] = 0.0f; }
}

// ---------------- tensor-core GEMM: Z = x @ Wcat (bf16x3 split) -----------
// 100000x128 @ 128x640. Tile 128(M) x 128(N) x 32(K). 512 threads = 16 warps,
// each warp computes 32x32 via m16n8k16 bf16 HMMA with fp32 accumulation.
// x split to bf16 hi/lo on the fly; W pre-split. Z = xh@Wh + xh@Wl + xl@Wh.
__device__ __forceinline__ void mma16816(float* c, const unsigned* a,
                                         const unsigned* b) {
    asm volatile(
        "mma.sync.aligned.m16n8k16.row.col.f32.bf16.bf16.f32 "
        "{%0,%1,%2,%3}, {%4,%5,%6,%7}, {%8,%9}, {%0,%1,%2,%3};\n"
        : "+f"(c[0]), "+f"(c[1]), "+f"(c[2]), "+f"(c[3])
        : "r"(a[0]), "r"(a[1]), "r"(a[2]), "r"(a[3]), "r"(b[0]), "r"(b[1]));
}

__global__ __launch_bounds__(512) void k_gemm_tc(int layer,
                                                 const float* __restrict__ b_sl) {
    __shared__ __nv_bfloat16 xs[2][128][40];   // [hi/lo][m][k], row=80B: bank-clean
    __shared__ unsigned ws[2][16][136];        // [hi/lo][k2][n], stride-136: bank-clean

    const unsigned* __restrict__ Wh32 = reinterpret_cast<const unsigned*>(g_Wh);
    const unsigned* __restrict__ Wl32 = reinterpret_cast<const unsigned*>(g_Wl);

    int tid  = threadIdx.x;
    int lane = tid & 31;
    int wid  = tid >> 5;
    int g    = lane >> 2;       // groupID
    int tig  = lane & 3;        // thread in group
    int m_base = (wid & 3) * 32;
    int n_base = (wid >> 2) * 32;
    int m0 = blockIdx.x * 128;
    int n0 = blockIdx.y * 128;

    float C[2][4][4];
#pragma unroll
    for (int mt = 0; mt < 2; mt++)
#pragma unroll
        for (int nt = 0; nt < 4; nt++)
#pragma unroll
            for (int j = 0; j < 4; j++) C[mt][nt][j] = 0.0f;

    for (int kc = 0; kc < 4; kc++) {            // K chunks of 32
        // ---- load x tile (128 x 32 fp32), split to bf16 hi/lo ----
#pragma unroll
        for (int i = 0; i < 2; i++) {
            int lin = tid + i * 512;            // 1024 float4 total
            int row = lin >> 3;
            int q   = lin & 7;
            float4 v = make_float4(0.f, 0.f, 0.f, 0.f);
            if (m0 + row < N_ENT)
                v = *reinterpret_cast<const float4*>(
                        &g_x[(m0 + row) * DIM + kc * 32 + q * 4]);
            __nv_bfloat16 h0 = __float2bfloat16(v.x);
            __nv_bfloat16 h1 = __float2bfloat16(v.y);
            __nv_bfloat16 h2 = __float2bfloat16(v.z);
            __nv_bfloat16 h3 = __float2bfloat16(v.w);
            __nv_bfloat16 l0 = __float2bfloat16(v.x - __bfloat162float(h0));
            __nv_bfloat16 l1 = __float2bfloat16(v.y - __bfloat162float(h1));
            __nv_bfloat16 l2 = __float2bfloat16(v.z - __bfloat162float(h2));
            __nv_bfloat16 l3 = __float2bfloat16(v.w - __bfloat162float(h3));
            *reinterpret_cast<__nv_bfloat162*>(&xs[0][row][q * 4]) =
                __nv_bfloat162(h0, h1);
            *reinterpret_cast<__nv_bfloat162*>(&xs[0][row][q * 4 + 2]) =
                __nv_bfloat162(h2, h3);
            *reinterpret_cast<__nv_bfloat162*>(&xs[1][row][q * 4]) =
                __nv_bfloat162(l0, l1);
            *reinterpret_cast<__nv_bfloat162*>(&xs[1][row][q * 4 + 2]) =
                __nv_bfloat162(l2, l3);
        }
        // ---- load W tile (32k x 128n as 16 x 128 u32, hi+lo) ----
#pragma unroll
        for (int i = 0; i < 8; i++) {
            int lin = tid + i * 512;            // 4096 u32 total
            int h   = lin >> 11;
            int rem = lin & 2047;
            int r   = rem >> 7;
            int n   = rem & 127;
            int src = (layer * 64 + kc * 16 + r) * NCOLS + n0 + n;
            ws[h][r][n] = h ? Wl32[src] : Wh32[src];
        }
        __syncthreads();

#pragma unroll
        for (int s = 0; s < 2; s++) {           // two k16 steps per chunk
            unsigned Ah[2][4], Al[2][4];
#pragma unroll
            for (int mt = 0; mt < 2; mt++) {
                int r0 = m_base + mt * 16 + g;
                int c0 = s * 16 + tig * 2;
                Ah[mt][0] = *reinterpret_cast<const unsigned*>(&xs[0][r0][c0]);
                Ah[mt][1] = *reinterpret_cast<const unsigned*>(&xs[0][r0 + 8][c0]);
                Ah[mt][2] = *reinterpret_cast<const unsigned*>(&xs[0][r0][c0 + 8]);
                Ah[mt][3] = *reinterpret_cast<const unsigned*>(&xs[0][r0 + 8][c0 + 8]);
                Al[mt][0] = *reinterpret_cast<const unsigned*>(&xs[1][r0][c0]);
                Al[mt][1] = *reinterpret_cast<const unsigned*>(&xs[1][r0 + 8][c0]);
                Al[mt][2] = *reinterpret_cast<const unsigned*>(&xs[1][r0][c0 + 8]);
                Al[mt][3] = *reinterpret_cast<const unsigned*>(&xs[1][r0 + 8][c0 + 8]);
            }
            unsigned Bh[4][2], Bl[4][2];
#pragma unroll
            for (int nt = 0; nt < 4; nt++) {
                int n = n_base + nt * 8 + g;
                Bh[nt][0] = ws[0][s * 8 + tig][n];
                Bh[nt][1] = ws[0][s * 8 + 4 + tig][n];
                Bl[nt][0] = ws[1][s * 8 + tig][n];
                Bl[nt][1] = ws[1][s * 8 + 4 + tig][n];
            }
#pragma unroll
            for (int mt = 0; mt < 2; mt++)
#pragma unroll
                for (int nt = 0; nt < 4; nt++) {
                    mma16816(C[mt][nt], Ah[mt], Bh[nt]);
                    mma16816(C[mt][nt], Ah[mt], Bl[nt]);
                    mma16816(C[mt][nt], Al[mt], Bh[nt]);
                }
        }
        __syncthreads();
    }

    // ---- epilogue ----
    bool isOut = (blockIdx.y == 0);
    const float* __restrict__ bias = b_sl + layer * DIM;
#pragma unroll
    for (int mt = 0; mt < 2; mt++) {
#pragma unroll
        for (int nt = 0; nt < 4; nt++) {
            int col  = n_base + nt * 8 + tig * 2;   // local 0..127
            int row0 = m0 + m_base + mt * 16 + g;
            float b0 = 0.f, b1 = 0.f;
            if (isOut) { b0 = bias[col]; b1 = bias[col + 1]; }
            float2 v0 = make_float2(C[mt][nt][0] + b0, C[mt][nt][1] + b1);
            float2 v1 = make_float2(C[mt][nt][2] + b0, C[mt][nt][3] + b1);
            if (isOut) {
                if (row0 < N_ENT)
                    *reinterpret_cast<float2*>(&g_out[row0 * DIM + col]) = v0;
                if (row0 + 8 < N_ENT)
                    *reinterpret_cast<float2*>(&g_out[(row0 + 8) * DIM + col]) = v1;
            } else {
                int yc = n0 - DIM + col;
                if (row0 < N_ENT)
                    *reinterpret_cast<float2*>(&g_Y[row0 * 512 + yc]) = v0;
                if (row0 + 8 < N_ENT)
                    *reinterpret_cast<float2*>(&g_Y[(row0 + 8) * 512 + yc]) = v1;
            }
        }
    }
}

// ---------------- edge kernel: one warp per edge --------------------------
__global__ __launch_bounds__(256) void k_edge(const int* __restrict__ ei,
                                              const int* __restrict__ et,
                                              const float* __restrict__ coeff) {
    int warp = (blockIdx.x * blockDim.x + threadIdx.x) >> 5;
    int lane = threadIdx.x & 31;
    if (warp >= N_EDGES) return;

    int s = ei[warp];
    int d = ei[N_EDGES + warp];
    int t = et[warp];

    float4 c = *reinterpret_cast<const float4*>(&coeff[t * 4]);
    const float4* yr =
        reinterpret_cast<const float4*>(&g_Y[s * 512]) + lane;  // +32 per basis
    float4 y0 = yr[0], y1 = yr[32], y2 = yr[64], y3 = yr[96];

    float4 m;
    m.x = c.x * y0.x + c.y * y1.x + c.z * y2.x + c.w * y3.x;
    m.y = c.x * y0.y + c.y * y1.y + c.z * y2.y + c.w * y3.y;
    m.z = c.x * y0.z + c.y * y1.z + c.z * y2.z + c.w * y3.z;
    m.w = c.x * y0.w + c.y * y1.w + c.z * y2.w + c.w * y3.w;

    atomicAdd(reinterpret_cast<float4*>(&g_out[d * DIM + lane * 4]), m);
}

// ---------------- BN pass 1: divide by deg (in place) + column sums -------
__global__ __launch_bounds__(128) void k_bn_stats() {
    int col = threadIdx.x;
    int r0 = blockIdx.x * 256;
    int r1 = r0 + 256; if (r1 > N_ENT) r1 = N_ENT;
    float s = 0.0f, q = 0.0f;
    for (int r = r0; r < r1; r++) {
        float invd = 1.0f / fmaxf(g_deg[r], 1.0f);
        float v = g_out[r * DIM + col] * invd;
        g_out[r * DIM + col] = v;
        s += v;
        q += v * v;
    }
    atomicAdd(&g_sum[col], s);
    atomicAdd(&g_sumsq[col], q);
}

// ---------------- BN pass 2: normalize + affine + relu -> g_x -------------
__global__ __launch_bounds__(256) void k_bn_apply(int layer,
                                                  const float* __restrict__ gamma,
                                                  const float* __restrict__ beta) {
    const float INV_N = 1.0f / (float)N_ENT;
    int i = blockIdx.x * blockDim.x + threadIdx.x;    // float4 index
    int total = N_ENT * DIM / 4;
    if (i >= total) return;
    int c0 = (i & 31) * 4;
    float4 v  = reinterpret_cast<const float4*>(g_out)[i];
    float4 s4 = *reinterpret_cast<const float4*>(&g_sum[c0]);
    float4 q4 = *reinterpret_cast<const float4*>(&g_sumsq[c0]);
    float4 gm = *reinterpret_cast<const float4*>(&gamma[layer * DIM + c0]);
    float4 bt = *reinterpret_cast<const float4*>(&beta[layer * DIM + c0]);

    float4 o;
    {
        float mu = s4.x * INV_N; float var = q4.x * INV_N - mu * mu;
        o.x = fmaxf((v.x - mu) * rsqrtf(var + BN_EPS) * gm.x + bt.x, 0.f);
    }
    {
        float mu = s4.y * INV_N; float var = q4.y * INV_N - mu * mu;
        o.y = fmaxf((v.y - mu) * rsqrtf(var + BN_EPS) * gm.y + bt.y, 0.f);
    }
    {
        float mu = s4.z * INV_N; float var = q4.z * INV_N - mu * mu;
        o.z = fmaxf((v.z - mu) * rsqrtf(var + BN_EPS) * gm.z + bt.z, 0.f);
    }
    {
        float mu = s4.w * INV_N; float var = q4.w * INV_N - mu * mu;
        o.w = fmaxf((v.w - mu) * rsqrtf(var + BN_EPS) * gm.w + bt.w, 0.f);
    }
    reinterpret_cast<float4*>(g_x)[i] = o;
}

// ---------------- scoring: TransE distances -------------------------------
__global__ __launch_bounds__(256) void k_score(const int* __restrict__ head,
                                               const int* __restrict__ relidx,
                                               const int* __restrict__ tail,
                                               const int* __restrict__ neg,
                                               const float* __restrict__ rel_tab,
                                               float* __restrict__ out) {
    __shared__ float hr[DIM];
    int b = blockIdx.x;
    int tid = threadIdx.x;
    int h = head[b], r = relidx[b], t = tail[b];
    if (tid < DIM)
        hr[tid] = g_x[h * DIM + tid] + rel_tab[r * DIM + tid];
    __syncthreads();

    int wid = tid >> 5, lane = tid & 31;
    const float4* h4 = reinterpret_cast<const float4*>(hr);
    float4 hv = h4[lane];

    for (int j = wid; j < 1 + N_NEG; j += 8) {
        int target = (j == 0) ? t : neg[b * N_NEG + (j - 1)];
        float4 ev = reinterpret_cast<const float4*>(&g_x[target * DIM])[lane];
        float dx = hv.x - ev.x, dy = hv.y - ev.y,
              dz = hv.z - ev.z, dw = hv.w - ev.w;
        float sum = dx * dx + dy * dy + dz * dz + dw * dw;
#pragma unroll
        for (int off = 16; off > 0; off >>= 1)
            sum += __shfl_xor_sync(0xffffffffu, sum, off);
        if (lane == 0) {
            float sc = -sqrtf(sum);
            if (j == 0) out[b] = sc;
            else        out[BATCH + b * N_NEG + (j - 1)] = sc;
        }
    }
}

// ---------------- launcher ------------------------------------------------
extern "C" void kernel_launch(void* const* d_in, const int* in_sizes, int n_in,
                              void* d_out, int out_size) {
    const int*   head    = (const int*)d_in[0];
    const int*   relidx  = (const int*)d_in[1];
    const int*   tail    = (const int*)d_in[2];
    const int*   neg     = (const int*)d_in[3];
    const int*   ei      = (const int*)d_in[4];
    const int*   et      = (const int*)d_in[5];
    const float* ent_tab = (const float*)d_in[6];
    const float* rel_tab = (const float*)d_in[7];
    const float* bases   = (const float*)d_in[8];
    const float* coeffs  = (const float*)d_in[9];
    const float* w_sl    = (const float*)d_in[10];
    const float* b_sl    = (const float*)d_in[11];
    const float* gamma   = (const float*)d_in[12];
    const float* beta    = (const float*)d_in[13];
    float* out = (float*)d_out;

    // setup
    k_copy_x<<<(N_ENT * DIM / 4 + 255) / 256, 256>>>(ent_tab);
    k_zero_deg<<<(N_ENT + 255) / 256, 256>>>();
    k_deg<<<(N_EDGES + 255) / 256, 256>>>(ei);
    k_wcat<<<(2 * DIM * NCOLS + 255) / 256, 256>>>(w_sl, bases);

    dim3 ggrid((N_ENT + 127) / 128, NCOLS / 128);
    for (int l = 0; l < 2; l++) {
        k_gemm_tc<<<ggrid, 512>>>(l, b_sl);
        k_edge<<<(N_EDGES * 32 + 255) / 256, 256>>>(ei, et, coeffs + l * N_REL * N_BASES);
        k_zero_stats<<<1, 128>>>();
        k_bn_stats<<<(N_ENT + 255) / 256, 128>>>();
        k_bn_apply<<<(N_ENT * DIM / 4 + 255) / 256, 256>>>(l, gamma, beta);
    }

    k_score<<<BATCH, 256>>>(head, relidx, tail, neg, rel_tab, out);
}

// round 6
// speedup vs baseline: 1.3981x; 1.1219x over previous
#include <cuda_runtime.h>
#include <cuda_bf16.h>
#include <math.h>

#define N_ENT    100000
#define N_REL    16
#define DIM      128
#define N_BASES  4
#define N_EDGES  640000
#define BATCH    1024
#define N_NEG    64
#define NCOLS    640          // 128 self-loop + 4*128 basis projections
#define BN_EPS   1e-5f
#define NSCANB   391          // ceil(N_ENT/256)

// ---------------- device scratch (static) ---------------------------------
__device__ float g_out0[N_ENT * DIM];     // layer-0 pre-BN accumulator
__device__ float g_out1[N_ENT * DIM];     // layer-1 pre-BN accumulator
__device__ float g_Y[N_ENT * 512];        // 4 basis projections (205 MB)
__device__ float g_deg[N_ENT];
__device__ float g_sum[DIM];
__device__ float g_sumsq[DIM];
__device__ float g_scale[DIM];            // BN fused scale  (rs*gamma)
__device__ float g_shift[DIM];            // BN fused shift  (beta - mu*rs*gamma)
// counting sort of edges by src
__device__ int g_hist[N_ENT];
__device__ int g_histL[N_ENT];
__device__ int g_bsum[NSCANB];
__device__ int g_cursor[N_ENT];
__device__ int g_es[N_EDGES];
__device__ int g_ed[N_EDGES];
__device__ int g_et[N_EDGES];
// W split into bf16 hi/lo, k-pair-interleaved:
// u32 index (l, k2, n) packs { W[2*k2][n], W[2*k2+1][n] }
__device__ __nv_bfloat16 g_Wh[2 * 64 * NCOLS * 2];
__device__ __nv_bfloat16 g_Wl[2 * 64 * NCOLS * 2];

// ---------------- setup ---------------------------------------------------
__global__ void k_zero_all() {
    int i = blockIdx.x * blockDim.x + threadIdx.x;
    if (i < N_ENT) { g_deg[i] = 0.0f; g_hist[i] = 0; g_cursor[i] = 0; }
}

__global__ void k_deg_hist(const int* __restrict__ ei) {
    int e = blockIdx.x * blockDim.x + threadIdx.x;
    if (e < N_EDGES) {
        atomicAdd(&g_deg[ei[N_EDGES + e]], 1.0f);
        atomicAdd(&g_hist[ei[e]], 1);
    }
}

// per-block inclusive scan (Hillis-Steele, 256) -> local exclusive + block sums
__global__ __launch_bounds__(256) void k_scan_part() {
    __shared__ int sm[256];
    int t = threadIdx.x;
    int idx = blockIdx.x * 256 + t;
    int v = (idx < N_ENT) ? g_hist[idx] : 0;
    int x = v;
    sm[t] = x; __syncthreads();
#pragma unroll
    for (int off = 1; off < 256; off <<= 1) {
        int y = (t >= off) ? sm[t - off] : 0;
        __syncthreads();
        x += y; sm[t] = x;
        __syncthreads();
    }
    if (idx < N_ENT) g_histL[idx] = x - v;
    if (t == 255) g_bsum[blockIdx.x] = x;
}

// single-block exclusive scan of the 391 block sums
__global__ __launch_bounds__(512) void k_scan_blk() {
    __shared__ int sm[512];
    int t = threadIdx.x;
    int v = (t < NSCANB) ? g_bsum[t] : 0;
    int x = v;
    sm[t] = x; __syncthreads();
#pragma unroll
    for (int off = 1; off < 512; off <<= 1) {
        int y = (t >= off) ? sm[t - off] : 0;
        __syncthreads();
        x += y; sm[t] = x;
        __syncthreads();
    }
    if (t < NSCANB) g_bsum[t] = x - v;   // exclusive
}

__global__ void k_scatter(const int* __restrict__ ei,
                          const int* __restrict__ et) {
    int e = blockIdx.x * blockDim.x + threadIdx.x;
    if (e >= N_EDGES) return;
    int s = ei[e];
    int d = ei[N_EDGES + e];
    int t = et[e];
    int pos = g_histL[s] + g_bsum[s >> 8] + atomicAdd(&g_cursor[s], 1);
    g_es[pos] = s; g_ed[pos] = d; g_et[pos] = t;
}

// build fused weight [w_sl | B0..B3], split to bf16 hi/lo, k-pair-interleaved
__global__ void k_wcat(const float* __restrict__ w_sl,
                       const float* __restrict__ bases) {
    int idx = blockIdx.x * blockDim.x + threadIdx.x;
    int total = 2 * DIM * NCOLS;
    if (idx >= total) return;
    int l   = idx / (DIM * NCOLS);
    int rem = idx - l * (DIM * NCOLS);
    int k   = rem / NCOLS;
    int n   = rem - k * NCOLS;
    float v;
    if (n < DIM) {
        v = w_sl[l * DIM * DIM + k * DIM + n];
    } else {
        int b = (n - DIM) >> 7;
        int f = (n - DIM) & 127;
        v = bases[l * N_BASES * DIM * DIM + b * DIM * DIM + k * DIM + f];
    }
    __nv_bfloat16 hi = __float2bfloat16(v);
    __nv_bfloat16 lo = __float2bfloat16(v - __bfloat162float(hi));
    int dst = ((l * 64 + (k >> 1)) * NCOLS + n) * 2 + (k & 1);
    g_Wh[dst] = hi;
    g_Wl[dst] = lo;
}

__global__ void k_zero_stats() {
    int t = threadIdx.x;
    if (t < DIM) { g_sum[t] = 0.0f; g_sumsq[t] = 0.0f; }
}

// ---------------- tensor-core GEMM: Z = x @ Wcat (bf16x3 split) -----------
// bnflag==0: xsrc = ent_tab (kernel arg), writes g_out0.
// bnflag==1: xsrc = BN(g_out0) (device symbol), writes g_out1.
__device__ __forceinline__ void mma16816(float* c, const unsigned* a,
                                         const unsigned* b) {
    asm volatile(
        "mma.sync.aligned.m16n8k16.row.col.f32.bf16.bf16.f32 "
        "{%0,%1,%2,%3}, {%4,%5,%6,%7}, {%8,%9}, {%0,%1,%2,%3};\n"
        : "+f"(c[0]), "+f"(c[1]), "+f"(c[2]), "+f"(c[3])
        : "r"(a[0]), "r"(a[1]), "r"(a[2]), "r"(a[3]), "r"(b[0]), "r"(b[1]));
}

__global__ __launch_bounds__(512) void k_gemm_tc(int layer,
                                                 const float* __restrict__ xext,
                                                 const float* __restrict__ b_sl,
                                                 int bnflag) {
    __shared__ __nv_bfloat16 xs[2][128][40];   // [hi/lo][m][k]
    __shared__ unsigned ws[2][16][136];        // [hi/lo][k2][n]

    const unsigned* __restrict__ Wh32 = reinterpret_cast<const unsigned*>(g_Wh);
    const unsigned* __restrict__ Wl32 = reinterpret_cast<const unsigned*>(g_Wl);
    const float* __restrict__ xsrc = bnflag ? g_out0 : xext;
    float* __restrict__ outbuf = bnflag ? g_out1 : g_out0;

    int tid  = threadIdx.x;
    int lane = tid & 31;
    int wid  = tid >> 5;
    int g    = lane >> 2;
    int tig  = lane & 3;
    int m_base = (wid & 3) * 32;
    int n_base = (wid >> 2) * 32;
    int m0 = blockIdx.x * 128;
    int n0 = blockIdx.y * 128;

    float C[2][4][4];
#pragma unroll
    for (int mt = 0; mt < 2; mt++)
#pragma unroll
        for (int nt = 0; nt < 4; nt++)
#pragma unroll
            for (int j = 0; j < 4; j++) C[mt][nt][j] = 0.0f;

    for (int kc = 0; kc < 4; kc++) {
        // ---- load x tile (128 x 32 fp32), optional BN+ReLU, split hi/lo ----
#pragma unroll
        for (int i = 0; i < 2; i++) {
            int lin = tid + i * 512;
            int row = lin >> 3;
            int q   = lin & 7;
            int c0  = kc * 32 + q * 4;
            float4 v = make_float4(0.f, 0.f, 0.f, 0.f);
            if (m0 + row < N_ENT) {
                v = *reinterpret_cast<const float4*>(
                        &xsrc[(m0 + row) * DIM + c0]);
                if (bnflag) {
                    float invd = 1.0f / fmaxf(g_deg[m0 + row], 1.0f);
                    float4 sc = *reinterpret_cast<const float4*>(&g_scale[c0]);
                    float4 sh = *reinterpret_cast<const float4*>(&g_shift[c0]);
                    v.x = fmaxf(fmaf(v.x * invd, sc.x, sh.x), 0.f);
                    v.y = fmaxf(fmaf(v.y * invd, sc.y, sh.y), 0.f);
                    v.z = fmaxf(fmaf(v.z * invd, sc.z, sh.z), 0.f);
                    v.w = fmaxf(fmaf(v.w * invd, sc.w, sh.w), 0.f);
                }
            }
            __nv_bfloat16 h0 = __float2bfloat16(v.x);
            __nv_bfloat16 h1 = __float2bfloat16(v.y);
            __nv_bfloat16 h2 = __float2bfloat16(v.z);
            __nv_bfloat16 h3 = __float2bfloat16(v.w);
            __nv_bfloat16 l0 = __float2bfloat16(v.x - __bfloat162float(h0));
            __nv_bfloat16 l1 = __float2bfloat16(v.y - __bfloat162float(h1));
            __nv_bfloat16 l2 = __float2bfloat16(v.z - __bfloat162float(h2));
            __nv_bfloat16 l3 = __float2bfloat16(v.w - __bfloat162float(h3));
            *reinterpret_cast<__nv_bfloat162*>(&xs[0][row][q * 4]) =
                __nv_bfloat162(h0, h1);
            *reinterpret_cast<__nv_bfloat162*>(&xs[0][row][q * 4 + 2]) =
                __nv_bfloat162(h2, h3);
            *reinterpret_cast<__nv_bfloat162*>(&xs[1][row][q * 4]) =
                __nv_bfloat162(l0, l1);
            *reinterpret_cast<__nv_bfloat162*>(&xs[1][row][q * 4 + 2]) =
                __nv_bfloat162(l2, l3);
        }
        // ---- load W tile ----
#pragma unroll
        for (int i = 0; i < 8; i++) {
            int lin = tid + i * 512;
            int h   = lin >> 11;
            int rem = lin & 2047;
            int r   = rem >> 7;
            int n   = rem & 127;
            int src = (layer * 64 + kc * 16 + r) * NCOLS + n0 + n;
            ws[h][r][n] = h ? Wl32[src] : Wh32[src];
        }
        __syncthreads();

#pragma unroll
        for (int s = 0; s < 2; s++) {
            unsigned Ah[2][4], Al[2][4];
#pragma unroll
            for (int mt = 0; mt < 2; mt++) {
                int r0 = m_base + mt * 16 + g;
                int c0 = s * 16 + tig * 2;
                Ah[mt][0] = *reinterpret_cast<const unsigned*>(&xs[0][r0][c0]);
                Ah[mt][1] = *reinterpret_cast<const unsigned*>(&xs[0][r0 + 8][c0]);
                Ah[mt][2] = *reinterpret_cast<const unsigned*>(&xs[0][r0][c0 + 8]);
                Ah[mt][3] = *reinterpret_cast<const unsigned*>(&xs[0][r0 + 8][c0 + 8]);
                Al[mt][0] = *reinterpret_cast<const unsigned*>(&xs[1][r0][c0]);
                Al[mt][1] = *reinterpret_cast<const unsigned*>(&xs[1][r0 + 8][c0]);
                Al[mt][2] = *reinterpret_cast<const unsigned*>(&xs[1][r0][c0 + 8]);
                Al[mt][3] = *reinterpret_cast<const unsigned*>(&xs[1][r0 + 8][c0 + 8]);
            }
            unsigned Bh[4][2], Bl[4][2];
#pragma unroll
            for (int nt = 0; nt < 4; nt++) {
                int n = n_base + nt * 8 + g;
                Bh[nt][0] = ws[0][s * 8 + tig][n];
                Bh[nt][1] = ws[0][s * 8 + 4 + tig][n];
                Bl[nt][0] = ws[1][s * 8 + tig][n];
                Bl[nt][1] = ws[1][s * 8 + 4 + tig][n];
            }
#pragma unroll
            for (int mt = 0; mt < 2; mt++)
#pragma unroll
                for (int nt = 0; nt < 4; nt++) {
                    mma16816(C[mt][nt], Ah[mt], Bh[nt]);
                    mma16816(C[mt][nt], Ah[mt], Bl[nt]);
                    mma16816(C[mt][nt], Al[mt], Bh[nt]);
                }
        }
        __syncthreads();
    }

    // ---- epilogue ----
    bool isOut = (blockIdx.y == 0);
    const float* __restrict__ bias = b_sl + layer * DIM;
#pragma unroll
    for (int mt = 0; mt < 2; mt++) {
#pragma unroll
        for (int nt = 0; nt < 4; nt++) {
            int col  = n_base + nt * 8 + tig * 2;
            int row0 = m0 + m_base + mt * 16 + g;
            float b0 = 0.f, b1 = 0.f;
            if (isOut) { b0 = bias[col]; b1 = bias[col + 1]; }
            float2 v0 = make_float2(C[mt][nt][0] + b0, C[mt][nt][1] + b1);
            float2 v1 = make_float2(C[mt][nt][2] + b0, C[mt][nt][3] + b1);
            if (isOut) {
                if (row0 < N_ENT)
                    *reinterpret_cast<float2*>(&outbuf[row0 * DIM + col]) = v0;
                if (row0 + 8 < N_ENT)
                    *reinterpret_cast<float2*>(&outbuf[(row0 + 8) * DIM + col]) = v1;
            } else {
                int yc = n0 - DIM + col;
                if (row0 < N_ENT)
                    *reinterpret_cast<float2*>(&g_Y[row0 * 512 + yc]) = v0;
                if (row0 + 8 < N_ENT)
                    *reinterpret_cast<float2*>(&g_Y[(row0 + 8) * 512 + yc]) = v1;
            }
        }
    }
}

// ---------------- edge kernel (src-sorted): one warp per edge -------------
__global__ __launch_bounds__(256) void k_edge_s(const float* __restrict__ coeff,
                                                int outsel) {
    float* __restrict__ outbuf = outsel ? g_out1 : g_out0;
    int warp = (blockIdx.x * blockDim.x + threadIdx.x) >> 5;
    int lane = threadIdx.x & 31;
    if (warp >= N_EDGES) return;

    int s = g_es[warp];
    int d = g_ed[warp];
    int t = g_et[warp];

    float4 c = *reinterpret_cast<const float4*>(&coeff[t * 4]);
    const float4* __restrict__ yr =
        reinterpret_cast<const float4*>(&g_Y[s * 512]) + lane;
    float4 y0 = yr[0], y1 = yr[32], y2 = yr[64], y3 = yr[96];

    float4 m;
    m.x = c.x * y0.x + c.y * y1.x + c.z * y2.x + c.w * y3.x;
    m.y = c.x * y0.y + c.y * y1.y + c.z * y2.y + c.w * y3.y;
    m.z = c.x * y0.z + c.y * y1.z + c.z * y2.z + c.w * y3.z;
    m.w = c.x * y0.w + c.y * y1.w + c.z * y2.w + c.w * y3.w;

    atomicAdd(reinterpret_cast<float4*>(&outbuf[d * DIM + lane * 4]), m);
}

// ---------------- BN stats: divide by deg (not written back) + col sums ---
__global__ __launch_bounds__(256) void k_bn_stats(int outsel) {
    const float* __restrict__ outbuf = outsel ? g_out1 : g_out0;
    int tid  = threadIdx.x;
    int c4   = tid & 31;
    int rsub = tid >> 5;
    int r0   = blockIdx.x * 1024;
    float4 s = make_float4(0.f, 0.f, 0.f, 0.f);
    float4 q = make_float4(0.f, 0.f, 0.f, 0.f);
    for (int i = 0; i < 128; i++) {
        int r = r0 + rsub + i * 8;
        if (r < N_ENT) {
            float invd = 1.0f / fmaxf(g_deg[r], 1.0f);
            float4 v = *reinterpret_cast<const float4*>(&outbuf[r * DIM + c4 * 4]);
            v.x *= invd; v.y *= invd; v.z *= invd; v.w *= invd;
            s.x += v.x; s.y += v.y; s.z += v.z; s.w += v.w;
            q.x += v.x * v.x; q.y += v.y * v.y;
            q.z += v.z * v.z; q.w += v.w * v.w;
        }
    }
    atomicAdd(&g_sum[c4 * 4 + 0], s.x);
    atomicAdd(&g_sum[c4 * 4 + 1], s.y);
    atomicAdd(&g_sum[c4 * 4 + 2], s.z);
    atomicAdd(&g_sum[c4 * 4 + 3], s.w);
    atomicAdd(&g_sumsq[c4 * 4 + 0], q.x);
    atomicAdd(&g_sumsq[c4 * 4 + 1], q.y);
    atomicAdd(&g_sumsq[c4 * 4 + 2], q.z);
    atomicAdd(&g_sumsq[c4 * 4 + 3], q.w);
}

// ---------------- BN finalize: fused scale/shift per column ---------------
__global__ void k_bn_final(int layer, const float* __restrict__ gamma,
                           const float* __restrict__ beta) {
    int c = threadIdx.x;
    if (c >= DIM) return;
    const float INV_N = 1.0f / (float)N_ENT;
    float mu  = g_sum[c] * INV_N;
    float var = g_sumsq[c] * INV_N - mu * mu;
    float rs  = rsqrtf(var + BN_EPS);
    float sc  = rs * gamma[layer * DIM + c];
    g_scale[c] = sc;
    g_shift[c] = beta[layer * DIM + c] - mu * sc;
}

// ---------------- scoring (fused BN+ReLU on gathered rows) ----------------
__device__ __forceinline__ float4 bnrelu4(float4 v, float invd,
                                          float4 sc, float4 sh) {
    v.x = fmaxf(fmaf(v.x * invd, sc.x, sh.x), 0.f);
    v.y = fmaxf(fmaf(v.y * invd, sc.y, sh.y), 0.f);
    v.z = fmaxf(fmaf(v.z * invd, sc.z, sh.z), 0.f);
    v.w = fmaxf(fmaf(v.w * invd, sc.w, sh.w), 0.f);
    return v;
}

__global__ __launch_bounds__(256) void k_score(const int* __restrict__ head,
                                               const int* __restrict__ relidx,
                                               const int* __restrict__ tail,
                                               const int* __restrict__ neg,
                                               const float* __restrict__ rel_tab,
                                               float* __restrict__ out) {
    __shared__ float hr[DIM];
    int b = blockIdx.x;
    int tid = threadIdx.x;
    int h = head[b], r = relidx[b], t = tail[b];
    if (tid < DIM) {
        float invd = 1.0f / fmaxf(g_deg[h], 1.0f);
        float v = g_out1[h * DIM + tid];
        v = fmaxf(fmaf(v * invd, g_scale[tid], g_shift[tid]), 0.f);
        hr[tid] = v + rel_tab[r * DIM + tid];
    }
    __syncthreads();

    int wid = tid >> 5, lane = tid & 31;
    float4 hv = reinterpret_cast<const float4*>(hr)[lane];
    float4 sc = *reinterpret_cast<const float4*>(&g_scale[lane * 4]);
    float4 sh = *reinterpret_cast<const float4*>(&g_shift[lane * 4]);

    for (int j = wid; j < 1 + N_NEG; j += 8) {
        int target = (j == 0) ? t : neg[b * N_NEG + (j - 1)];
        float invd = 1.0f / fmaxf(g_deg[target], 1.0f);
        float4 ev = reinterpret_cast<const float4*>(&g_out1[target * DIM])[lane];
        ev = bnrelu4(ev, invd, sc, sh);
        float dx = hv.x - ev.x, dy = hv.y - ev.y,
              dz = hv.z - ev.z, dw = hv.w - ev.w;
        float sum = dx * dx + dy * dy + dz * dz + dw * dw;
#pragma unroll
        for (int off = 16; off > 0; off >>= 1)
            sum += __shfl_xor_sync(0xffffffffu, sum, off);
        if (lane == 0) {
            float scv = -sqrtf(sum);
            if (j == 0) out[b] = scv;
            else        out[BATCH + b * N_NEG + (j - 1)] = scv;
        }
    }
}

// ---------------- launcher ------------------------------------------------
extern "C" void kernel_launch(void* const* d_in, const int* in_sizes, int n_in,
                              void* d_out, int out_size) {
    const int*   head    = (const int*)d_in[0];
    const int*   relidx  = (const int*)d_in[1];
    const int*   tail    = (const int*)d_in[2];
    const int*   neg     = (const int*)d_in[3];
    const int*   ei      = (const int*)d_in[4];
    const int*   et      = (const int*)d_in[5];
    const float* ent_tab = (const float*)d_in[6];
    const float* rel_tab = (const float*)d_in[7];
    const float* bases   = (const float*)d_in[8];
    const float* coeffs  = (const float*)d_in[9];
    const float* w_sl    = (const float*)d_in[10];
    const float* b_sl    = (const float*)d_in[11];
    const float* gamma   = (const float*)d_in[12];
    const float* beta    = (const float*)d_in[13];
    float* out = (float*)d_out;

    // deg + counting sort of edges by src (reused for both layers)
    k_zero_all<<<(N_ENT + 255) / 256, 256>>>();
    k_deg_hist<<<(N_EDGES + 255) / 256, 256>>>(ei);
    k_scan_part<<<NSCANB, 256>>>();
    k_scan_blk<<<1, 512>>>();
    k_scatter<<<(N_EDGES + 255) / 256, 256>>>(ei, et);
    k_wcat<<<(2 * DIM * NCOLS + 255) / 256, 256>>>(w_sl, bases);

    dim3 ggrid((N_ENT + 127) / 128, NCOLS / 128);

    // layer 0: x = ent_tab (no BN), out -> g_out0
    k_gemm_tc<<<ggrid, 512>>>(0, ent_tab, b_sl, 0);
    k_edge_s<<<(N_EDGES * 32 + 255) / 256, 256>>>(coeffs, 0);
    k_zero_stats<<<1, 128>>>();
    k_bn_stats<<<(N_ENT + 1023) / 1024, 256>>>(0);
    k_bn_final<<<1, 128>>>(0, gamma, beta);

    // layer 1: x = BN(g_out0) (internal), out -> g_out1
    k_gemm_tc<<<ggrid, 512>>>(1, ent_tab, b_sl, 1);
    k_edge_s<<<(N_EDGES * 32 + 255) / 256, 256>>>(coeffs + N_REL * N_BASES, 1);
    k_zero_stats<<<1, 128>>>();
    k_bn_stats<<<(N_ENT + 1023) / 1024, 256>>>(1);
    k_bn_final<<<1, 128>>>(1, gamma, beta);

    // scoring with fused BN on gathered rows
    k_score<<<BATCH, 256>>>(head, relidx, tail, neg, rel_tab, out);
}

// round 7
// speedup vs baseline: 1.6274x; 1.1640x over previous
#include <cuda_runtime.h>
#include <cuda_bf16.h>
#include <math.h>

#define N_ENT    100000
#define N_REL    16
#define DIM      128
#define N_BASES  4
#define N_EDGES  640000
#define BATCH    1024
#define N_NEG    64
#define NCOLS    640          // 128 self-loop + 4*128 basis projections
#define BN_EPS   1e-5f
#define NSCANB   391          // ceil(N_ENT/256)

#define XS_STRIDE 136         // bf16 elems per xs row (272 B, 16B-aligned)
#define WS_STRIDE 20          // u32 per ws row (80 B, 16B-aligned)
#define SMEM_XS   (2 * 128 * XS_STRIDE * 2)               // 69632 B
#define SMEM_WS   (2 * 128 * WS_STRIDE * 4)               // 40960 B
#define SMEM_GEMM (SMEM_XS + SMEM_WS)                     // 110592 B

// ---------------- device scratch (static) ---------------------------------
__device__ float g_out0[N_ENT * DIM];     // layer-0 pre-BN accumulator
__device__ float g_out1[N_ENT * DIM];     // layer-1 pre-BN accumulator
__device__ float g_Y[N_ENT * 512];        // 4 basis projections (205 MB)
__device__ float g_deg[N_ENT];
__device__ float g_sum[DIM];
__device__ float g_sumsq[DIM];
__device__ float g_scale[DIM];            // BN fused scale  (rs*gamma)
__device__ float g_shift[DIM];            // BN fused shift  (beta - mu*rs*gamma)
// counting sort of edges by src
__device__ int g_hist[N_ENT];
__device__ int g_histL[N_ENT];
__device__ int g_bsum[NSCANB];
__device__ int g_cursor[N_ENT];
__device__ int g_es[N_EDGES];
__device__ int g_ed[N_EDGES];
__device__ int g_et[N_EDGES];
// W hi/lo, u32 k-pair packed, layout [l][n][k2]: idx = (l*NCOLS+n)*64 + k2
__device__ unsigned g_W32h[2 * NCOLS * 64];
__device__ unsigned g_W32l[2 * NCOLS * 64];

// ---------------- setup ---------------------------------------------------
__global__ void k_zero_all() {
    int i = blockIdx.x * blockDim.x + threadIdx.x;
    if (i < N_ENT) { g_deg[i] = 0.0f; g_hist[i] = 0; g_cursor[i] = 0; }
}

__global__ void k_deg_hist(const int* __restrict__ ei) {
    int e = blockIdx.x * blockDim.x + threadIdx.x;
    if (e < N_EDGES) {
        atomicAdd(&g_deg[ei[N_EDGES + e]], 1.0f);
        atomicAdd(&g_hist[ei[e]], 1);
    }
}

__global__ __launch_bounds__(256) void k_scan_part() {
    __shared__ int sm[256];
    int t = threadIdx.x;
    int idx = blockIdx.x * 256 + t;
    int v = (idx < N_ENT) ? g_hist[idx] : 0;
    int x = v;
    sm[t] = x; __syncthreads();
#pragma unroll
    for (int off = 1; off < 256; off <<= 1) {
        int y = (t >= off) ? sm[t - off] : 0;
        __syncthreads();
        x += y; sm[t] = x;
        __syncthreads();
    }
    if (idx < N_ENT) g_histL[idx] = x - v;
    if (t == 255) g_bsum[blockIdx.x] = x;
}

__global__ __launch_bounds__(512) void k_scan_blk() {
    __shared__ int sm[512];
    int t = threadIdx.x;
    int v = (t < NSCANB) ? g_bsum[t] : 0;
    int x = v;
    sm[t] = x; __syncthreads();
#pragma unroll
    for (int off = 1; off < 512; off <<= 1) {
        int y = (t >= off) ? sm[t - off] : 0;
        __syncthreads();
        x += y; sm[t] = x;
        __syncthreads();
    }
    if (t < NSCANB) g_bsum[t] = x - v;   // exclusive
}

__global__ void k_scatter(const int* __restrict__ ei,
                          const int* __restrict__ et) {
    int e = blockIdx.x * blockDim.x + threadIdx.x;
    if (e >= N_EDGES) return;
    int s = ei[e];
    int d = ei[N_EDGES + e];
    int t = et[e];
    int pos = g_histL[s] + g_bsum[s >> 8] + atomicAdd(&g_cursor[s], 1);
    g_es[pos] = s; g_ed[pos] = d; g_et[pos] = t;
}

// fused weight [w_sl | B0..B3] -> bf16 hi/lo u32 k-pairs, layout [l][n][k2]
__global__ void k_wcat(const float* __restrict__ w_sl,
                       const float* __restrict__ bases) {
    int idx = blockIdx.x * blockDim.x + threadIdx.x;
    int total = 2 * NCOLS * 64;
    if (idx >= total) return;
    int l   = idx / (NCOLS * 64);
    int rem = idx - l * (NCOLS * 64);
    int n   = rem >> 6;
    int k2  = rem & 63;
    float v0, v1;
    if (n < DIM) {
        v0 = w_sl[l * DIM * DIM + (2 * k2) * DIM + n];
        v1 = w_sl[l * DIM * DIM + (2 * k2 + 1) * DIM + n];
    } else {
        int b = (n - DIM) >> 7;
        int f = (n - DIM) & 127;
        const float* bp = bases + l * N_BASES * DIM * DIM + b * DIM * DIM;
        v0 = bp[(2 * k2) * DIM + f];
        v1 = bp[(2 * k2 + 1) * DIM + f];
    }
    __nv_bfloat16 h0 = __float2bfloat16(v0);
    __nv_bfloat16 h1 = __float2bfloat16(v1);
    __nv_bfloat16 l0 = __float2bfloat16(v0 - __bfloat162float(h0));
    __nv_bfloat16 l1 = __float2bfloat16(v1 - __bfloat162float(h1));
    __nv_bfloat162 ph(h0, h1), pl(l0, l1);
    g_W32h[idx] = *reinterpret_cast<unsigned*>(&ph);
    g_W32l[idx] = *reinterpret_cast<unsigned*>(&pl);
}

__global__ void k_zero_stats() {
    int t = threadIdx.x;
    if (t < DIM) { g_sum[t] = 0.0f; g_sumsq[t] = 0.0f; }
}

// ---------------- tensor-core GEMM: Z = x @ Wcat (bf16x3 split) -----------
__device__ __forceinline__ void mma16816(float* c, const unsigned* a,
                                         const unsigned* b) {
    asm volatile(
        "mma.sync.aligned.m16n8k16.row.col.f32.bf16.bf16.f32 "
        "{%0,%1,%2,%3}, {%4,%5,%6,%7}, {%8,%9}, {%0,%1,%2,%3};\n"
        : "+f"(c[0]), "+f"(c[1]), "+f"(c[2]), "+f"(c[3])
        : "r"(a[0]), "r"(a[1]), "r"(a[2]), "r"(a[3]), "r"(b[0]), "r"(b[1]));
}

__device__ __forceinline__ void ldsm4(unsigned* r, const void* p) {
    unsigned addr = (unsigned)__cvta_generic_to_shared(p);
    asm volatile(
        "ldmatrix.sync.aligned.m8n8.x4.shared.b16 {%0,%1,%2,%3}, [%4];"
        : "=r"(r[0]), "=r"(r[1]), "=r"(r[2]), "=r"(r[3]) : "r"(addr));
}

__global__ __launch_bounds__(512) void k_gemm_tc(int layer,
                                                 const float* __restrict__ xext,
                                                 const float* __restrict__ b_sl,
                                                 int bnflag) {
    extern __shared__ unsigned char smraw[];
    __nv_bfloat16* xs = reinterpret_cast<__nv_bfloat16*>(smraw);
    unsigned* ws = reinterpret_cast<unsigned*>(smraw + SMEM_XS);
    // XS(h,r,c) = xs[(h*128+r)*XS_STRIDE + c]
    // WS(h,n,k) = ws[(h*128+n)*WS_STRIDE + k]

    const float* __restrict__ xsrc = bnflag ? g_out0 : xext;
    float* __restrict__ outbuf = bnflag ? g_out1 : g_out0;

    int tid  = threadIdx.x;
    int lane = tid & 31;
    int wid  = tid >> 5;
    int g    = lane >> 2;
    int tig  = lane & 3;
    int m_base = (wid & 3) * 32;
    int n_base = (wid >> 2) * 32;
    int m0 = blockIdx.x * 128;

    // ---- load x tile (128 rows x 128 k) ONCE, BN+ReLU opt, split hi/lo ----
#pragma unroll
    for (int i = 0; i < 8; i++) {
        int lin = tid + i * 512;          // 0..4095 float4
        int row = lin >> 5;
        int q   = lin & 31;
        int c0  = q * 4;
        float4 v = make_float4(0.f, 0.f, 0.f, 0.f);
        if (m0 + row < N_ENT) {
            v = *reinterpret_cast<const float4*>(&xsrc[(m0 + row) * DIM + c0]);
            if (bnflag) {
                float invd = 1.0f / fmaxf(g_deg[m0 + row], 1.0f);
                float4 sc = *reinterpret_cast<const float4*>(&g_scale[c0]);
                float4 sh = *reinterpret_cast<const float4*>(&g_shift[c0]);
                v.x = fmaxf(fmaf(v.x * invd, sc.x, sh.x), 0.f);
                v.y = fmaxf(fmaf(v.y * invd, sc.y, sh.y), 0.f);
                v.z = fmaxf(fmaf(v.z * invd, sc.z, sh.z), 0.f);
                v.w = fmaxf(fmaf(v.w * invd, sc.w, sh.w), 0.f);
            }
        }
        __nv_bfloat16 h0 = __float2bfloat16(v.x);
        __nv_bfloat16 h1 = __float2bfloat16(v.y);
        __nv_bfloat16 h2 = __float2bfloat16(v.z);
        __nv_bfloat16 h3 = __float2bfloat16(v.w);
        __nv_bfloat16 l0 = __float2bfloat16(v.x - __bfloat162float(h0));
        __nv_bfloat16 l1 = __float2bfloat16(v.y - __bfloat162float(h1));
        __nv_bfloat16 l2 = __float2bfloat16(v.z - __bfloat162float(h2));
        __nv_bfloat16 l3 = __float2bfloat16(v.w - __bfloat162float(h3));
        __nv_bfloat16* xh = &xs[row * XS_STRIDE + c0];
        __nv_bfloat16* xl = &xs[(128 + row) * XS_STRIDE + c0];
        *reinterpret_cast<__nv_bfloat162*>(xh)     = __nv_bfloat162(h0, h1);
        *reinterpret_cast<__nv_bfloat162*>(xh + 2) = __nv_bfloat162(h2, h3);
        *reinterpret_cast<__nv_bfloat162*>(xl)     = __nv_bfloat162(l0, l1);
        *reinterpret_cast<__nv_bfloat162*>(xl + 2) = __nv_bfloat162(l2, l3);
    }
    __syncthreads();

    // ldmatrix source addresses (constant across iterations except kc/s/ntile)
    int a_row = m_base + (lane & 15);             // + mt*16
    int a_colsel = (lane >> 4) << 3;              // 0 or 8 (k-halves)
    int b_row = n_base + (lane & 7) + ((lane & 16) ? 8 : 0);   // + nt2*16
    int b_ksel = (lane & 8) ? 4 : 0;              // +4 u32 for k-hi matrices

    const float* __restrict__ bias = b_sl + layer * DIM;

    for (int ntile = 0; ntile < 5; ntile++) {
        int n0 = ntile * 128;
        float C[2][4][4];
#pragma unroll
        for (int mt = 0; mt < 2; mt++)
#pragma unroll
            for (int nt = 0; nt < 4; nt++)
#pragma unroll
                for (int j = 0; j < 4; j++) C[mt][nt][j] = 0.0f;

        for (int kc = 0; kc < 4; kc++) {
            if (ntile | kc) __syncthreads();      // protect ws reuse
            // ---- fill W tile: [h][n 0..127][k2 0..15] ----
#pragma unroll
            for (int i = 0; i < 8; i++) {
                int lin = tid + i * 512;          // 0..4095
                int h   = lin >> 11;
                int rem = lin & 2047;
                int n   = rem >> 4;
                int k2  = rem & 15;
                unsigned v = (h ? g_W32l : g_W32h)
                                 [(layer * NCOLS + n0 + n) * 64 + kc * 16 + k2];
                ws[(h * 128 + n) * WS_STRIDE + k2] = v;
            }
            __syncthreads();

#pragma unroll
            for (int s = 0; s < 2; s++) {
                unsigned A[2][2][4];              // [h][mt]
#pragma unroll
                for (int h = 0; h < 2; h++)
#pragma unroll
                    for (int mt = 0; mt < 2; mt++)
                        ldsm4(A[h][mt],
                              &xs[(h * 128 + a_row + mt * 16) * XS_STRIDE +
                                  kc * 32 + s * 16 + a_colsel]);
                unsigned B[2][2][4];              // [h][nt2]
#pragma unroll
                for (int h = 0; h < 2; h++)
#pragma unroll
                    for (int nt2 = 0; nt2 < 2; nt2++)
                        ldsm4(B[h][nt2],
                              &ws[(h * 128 + b_row + nt2 * 16) * WS_STRIDE +
                                  s * 8 + b_ksel]);
#pragma unroll
                for (int mt = 0; mt < 2; mt++)
#pragma unroll
                    for (int nt = 0; nt < 4; nt++) {
                        const unsigned* bh = &B[0][nt >> 1][(nt & 1) * 2];
                        const unsigned* bl = &B[1][nt >> 1][(nt & 1) * 2];
                        mma16816(C[mt][nt], A[0][mt], bh);
                        mma16816(C[mt][nt], A[0][mt], bl);
                        mma16816(C[mt][nt], A[1][mt], bh);
                    }
            }
        }

        // ---- epilogue for this n-tile ----
        bool isOut = (ntile == 0);
#pragma unroll
        for (int mt = 0; mt < 2; mt++) {
#pragma unroll
            for (int nt = 0; nt < 4; nt++) {
                int col  = n_base + nt * 8 + tig * 2;
                int row0 = m0 + m_base + mt * 16 + g;
                float b0 = 0.f, b1 = 0.f;
                if (isOut) { b0 = bias[col]; b1 = bias[col + 1]; }
                float2 v0 = make_float2(C[mt][nt][0] + b0, C[mt][nt][1] + b1);
                float2 v1 = make_float2(C[mt][nt][2] + b0, C[mt][nt][3] + b1);
                if (isOut) {
                    if (row0 < N_ENT)
                        *reinterpret_cast<float2*>(&outbuf[row0 * DIM + col]) = v0;
                    if (row0 + 8 < N_ENT)
                        *reinterpret_cast<float2*>(&outbuf[(row0 + 8) * DIM + col]) = v1;
                } else {
                    int yc = n0 - DIM + col;
                    if (row0 < N_ENT)
                        *reinterpret_cast<float2*>(&g_Y[row0 * 512 + yc]) = v0;
                    if (row0 + 8 < N_ENT)
                        *reinterpret_cast<float2*>(&g_Y[(row0 + 8) * 512 + yc]) = v1;
                }
            }
        }
    }
}

// ---------------- edge kernel (src-sorted): one warp per edge -------------
__global__ __launch_bounds__(256) void k_edge_s(const float* __restrict__ coeff,
                                                int outsel) {
    float* __restrict__ outbuf = outsel ? g_out1 : g_out0;
    int warp = (blockIdx.x * blockDim.x + threadIdx.x) >> 5;
    int lane = threadIdx.x & 31;
    if (warp >= N_EDGES) return;

    int s = g_es[warp];
    int d = g_ed[warp];
    int t = g_et[warp];

    float4 c = *reinterpret_cast<const float4*>(&coeff[t * 4]);
    const float4* __restrict__ yr =
        reinterpret_cast<const float4*>(&g_Y[s * 512]) + lane;
    float4 y0 = yr[0], y1 = yr[32], y2 = yr[64], y3 = yr[96];

    float4 m;
    m.x = c.x * y0.x + c.y * y1.x + c.z * y2.x + c.w * y3.x;
    m.y = c.x * y0.y + c.y * y1.y + c.z * y2.y + c.w * y3.y;
    m.z = c.x * y0.z + c.y * y1.z + c.z * y2.z + c.w * y3.z;
    m.w = c.x * y0.w + c.y * y1.w + c.z * y2.w + c.w * y3.w;

    atomicAdd(reinterpret_cast<float4*>(&outbuf[d * DIM + lane * 4]), m);
}

// ---------------- BN stats ------------------------------------------------
__global__ __launch_bounds__(256) void k_bn_stats(int outsel) {
    const float* __restrict__ outbuf = outsel ? g_out1 : g_out0;
    int tid  = threadIdx.x;
    int c4   = tid & 31;
    int rsub = tid >> 5;
    int r0   = blockIdx.x * 1024;
    float4 s = make_float4(0.f, 0.f, 0.f, 0.f);
    float4 q = make_float4(0.f, 0.f, 0.f, 0.f);
    for (int i = 0; i < 128; i++) {
        int r = r0 + rsub + i * 8;
        if (r < N_ENT) {
            float invd = 1.0f / fmaxf(g_deg[r], 1.0f);
            float4 v = *reinterpret_cast<const float4*>(&outbuf[r * DIM + c4 * 4]);
            v.x *= invd; v.y *= invd; v.z *= invd; v.w *= invd;
            s.x += v.x; s.y += v.y; s.z += v.z; s.w += v.w;
            q.x += v.x * v.x; q.y += v.y * v.y;
            q.z += v.z * v.z; q.w += v.w * v.w;
        }
    }
    atomicAdd(&g_sum[c4 * 4 + 0], s.x);
    atomicAdd(&g_sum[c4 * 4 + 1], s.y);
    atomicAdd(&g_sum[c4 * 4 + 2], s.z);
    atomicAdd(&g_sum[c4 * 4 + 3], s.w);
    atomicAdd(&g_sumsq[c4 * 4 + 0], q.x);
    atomicAdd(&g_sumsq[c4 * 4 + 1], q.y);
    atomicAdd(&g_sumsq[c4 * 4 + 2], q.z);
    atomicAdd(&g_sumsq[c4 * 4 + 3], q.w);
}

// ---------------- BN finalize ---------------------------------------------
__global__ void k_bn_final(int layer, const float* __restrict__ gamma,
                           const float* __restrict__ beta) {
    int c = threadIdx.x;
    if (c >= DIM) return;
    const float INV_N = 1.0f / (float)N_ENT;
    float mu  = g_sum[c] * INV_N;
    float var = g_sumsq[c] * INV_N - mu * mu;
    float rs  = rsqrtf(var + BN_EPS);
    float sc  = rs * gamma[layer * DIM + c];
    g_scale[c] = sc;
    g_shift[c] = beta[layer * DIM + c] - mu * sc;
}

// ---------------- scoring -------------------------------------------------
__device__ __forceinline__ float4 bnrelu4(float4 v, float invd,
                                          float4 sc, float4 sh) {
    v.x = fmaxf(fmaf(v.x * invd, sc.x, sh.x), 0.f);
    v.y = fmaxf(fmaf(v.y * invd, sc.y, sh.y), 0.f);
    v.z = fmaxf(fmaf(v.z * invd, sc.z, sh.z), 0.f);
    v.w = fmaxf(fmaf(v.w * invd, sc.w, sh.w), 0.f);
    return v;
}

__global__ __launch_bounds__(256) void k_score(const int* __restrict__ head,
                                               const int* __restrict__ relidx,
                                               const int* __restrict__ tail,
                                               const int* __restrict__ neg,
                                               const float* __restrict__ rel_tab,
                                               float* __restrict__ out) {
    __shared__ float hr[DIM];
    int b = blockIdx.x;
    int tid = threadIdx.x;
    int h = head[b], r = relidx[b], t = tail[b];
    if (tid < DIM) {
        float invd = 1.0f / fmaxf(g_deg[h], 1.0f);
        float v = g_out1[h * DIM + tid];
        v = fmaxf(fmaf(v * invd, g_scale[tid], g_shift[tid]), 0.f);
        hr[tid] = v + rel_tab[r * DIM + tid];
    }
    __syncthreads();

    int wid = tid >> 5, lane = tid & 31;
    float4 hv = reinterpret_cast<const float4*>(hr)[lane];
    float4 sc = *reinterpret_cast<const float4*>(&g_scale[lane * 4]);
    float4 sh = *reinterpret_cast<const float4*>(&g_shift[lane * 4]);

    for (int j = wid; j < 1 + N_NEG; j += 8) {
        int target = (j == 0) ? t : neg[b * N_NEG + (j - 1)];
        float invd = 1.0f / fmaxf(g_deg[target], 1.0f);
        float4 ev = reinterpret_cast<const float4*>(&g_out1[target * DIM])[lane];
        ev = bnrelu4(ev, invd, sc, sh);
        float dx = hv.x - ev.x, dy = hv.y - ev.y,
              dz = hv.z - ev.z, dw = hv.w - ev.w;
        float sum = dx * dx + dy * dy + dz * dz + dw * dw;
#pragma unroll
        for (int off = 16; off > 0; off >>= 1)
            sum += __shfl_xor_sync(0xffffffffu, sum, off);
        if (lane == 0) {
            float scv = -sqrtf(sum);
            if (j == 0) out[b] = scv;
            else        out[BATCH + b * N_NEG + (j - 1)] = scv;
        }
    }
}

// ---------------- launcher ------------------------------------------------
extern "C" void kernel_launch(void* const* d_in, const int* in_sizes, int n_in,
                              void* d_out, int out_size) {
    const int*   head    = (const int*)d_in[0];
    const int*   relidx  = (const int*)d_in[1];
    const int*   tail    = (const int*)d_in[2];
    const int*   neg     = (const int*)d_in[3];
    const int*   ei      = (const int*)d_in[4];
    const int*   et      = (const int*)d_in[5];
    const float* ent_tab = (const float*)d_in[6];
    const float* rel_tab = (const float*)d_in[7];
    const float* bases   = (const float*)d_in[8];
    const float* coeffs  = (const float*)d_in[9];
    const float* w_sl    = (const float*)d_in[10];
    const float* b_sl    = (const float*)d_in[11];
    const float* gamma   = (const float*)d_in[12];
    const float* beta    = (const float*)d_in[13];
    float* out = (float*)d_out;

    cudaFuncSetAttribute(k_gemm_tc,
                         cudaFuncAttributeMaxDynamicSharedMemorySize, SMEM_GEMM);

    int ggrid = (N_ENT + 127) / 128;

    // launch #4 = layer-0 GEMM (so ncu -s5-c1 profiles it)
    k_zero_all<<<(N_ENT + 255) / 256, 256>>>();                    // 1
    k_deg_hist<<<(N_EDGES + 255) / 256, 256>>>(ei);                // 2
    k_wcat<<<(2 * NCOLS * 64 + 255) / 256, 256>>>(w_sl, bases);    // 3
    k_gemm_tc<<<ggrid, 512, SMEM_GEMM>>>(0, ent_tab, b_sl, 0);     // 4
    // edge sort (independent of gemm)
    k_scan_part<<<NSCANB, 256>>>();                                // 5
    k_scan_blk<<<1, 512>>>();                                      // 6
    k_scatter<<<(N_EDGES + 255) / 256, 256>>>(ei, et);             // 7

    // layer 0 rest
    k_edge_s<<<(N_EDGES * 32 + 255) / 256, 256>>>(coeffs, 0);
    k_zero_stats<<<1, 128>>>();
    k_bn_stats<<<(N_ENT + 1023) / 1024, 256>>>(0);
    k_bn_final<<<1, 128>>>(0, gamma, beta);

    // layer 1
    k_gemm_tc<<<ggrid, 512, SMEM_GEMM>>>(1, ent_tab, b_sl, 1);
    k_edge_s<<<(N_EDGES * 32 + 255) / 256, 256>>>(coeffs + N_REL * N_BASES, 1);
    k_zero_stats<<<1, 128>>>();
    k_bn_stats<<<(N_ENT + 1023) / 1024, 256>>>(1);
    k_bn_final<<<1, 128>>>(1, gamma, beta);

    // scoring with fused BN on gathered rows
    k_score<<<BATCH, 256>>>(head, relidx, tail, neg, rel_tab, out);
}

// round 8
// speedup vs baseline: 1.8236x; 1.1206x over previous
#include <cuda_runtime.h>
#include <cuda_bf16.h>
#include <math.h>

#define N_ENT    100000
#define N_REL    16
#define DIM      128
#define N_BASES  4
#define N_EDGES  640000
#define BATCH    1024
#define N_NEG    64
#define NCOLS    640          // 128 self-loop + 4*128 basis projections
#define BN_EPS   1e-5f
#define NSCANB   391          // ceil(N_ENT/256)

#define XS_STRIDE 136         // bf16 elems per xs row (272 B = 68 u32)
#define WS_STRIDE 68          // u32 per ws row (272 B), full K=128 (64 k2) + pad
#define WSBUF_U32 (2 * 128 * WS_STRIDE)                   // u32 per W buffer
#define SMEM_XS   (2 * 128 * XS_STRIDE * 2)               // 69632 B
#define SMEM_WS   (2 * WSBUF_U32 * 4)                     // 139264 B (double buf)
#define SMEM_GEMM (SMEM_XS + SMEM_WS)                     // 208896 B

// ---------------- device scratch (static) ---------------------------------
__device__ float g_out0[N_ENT * DIM];
__device__ float g_out1[N_ENT * DIM];
__device__ float g_Y[N_ENT * 512];
__device__ float g_deg[N_ENT];
__device__ float g_sum[DIM];
__device__ float g_sumsq[DIM];
__device__ float g_scale[DIM];
__device__ float g_shift[DIM];
__device__ int g_hist[N_ENT];
__device__ int g_histL[N_ENT];
__device__ int g_bsum[NSCANB];
__device__ int g_cursor[N_ENT];
__device__ int g_es[N_EDGES];
__device__ int g_ed[N_EDGES];
__device__ int g_et[N_EDGES];
// W hi/lo, u32 k-pair packed, layout [l][n][k2]: idx = (l*NCOLS+n)*64 + k2
__device__ unsigned g_W32h[2 * NCOLS * 64];
__device__ unsigned g_W32l[2 * NCOLS * 64];

// ---------------- setup ---------------------------------------------------
__global__ void k_zero_all() {
    int i = blockIdx.x * blockDim.x + threadIdx.x;
    if (i < N_ENT) { g_deg[i] = 0.0f; g_hist[i] = 0; g_cursor[i] = 0; }
}

__global__ void k_deg_hist(const int* __restrict__ ei) {
    int e = blockIdx.x * blockDim.x + threadIdx.x;
    if (e < N_EDGES) {
        atomicAdd(&g_deg[ei[N_EDGES + e]], 1.0f);
        atomicAdd(&g_hist[ei[e]], 1);
    }
}

__global__ __launch_bounds__(256) void k_scan_part() {
    __shared__ int sm[256];
    int t = threadIdx.x;
    int idx = blockIdx.x * 256 + t;
    int v = (idx < N_ENT) ? g_hist[idx] : 0;
    int x = v;
    sm[t] = x; __syncthreads();
#pragma unroll
    for (int off = 1; off < 256; off <<= 1) {
        int y = (t >= off) ? sm[t - off] : 0;
        __syncthreads();
        x += y; sm[t] = x;
        __syncthreads();
    }
    if (idx < N_ENT) g_histL[idx] = x - v;
    if (t == 255) g_bsum[blockIdx.x] = x;
}

__global__ __launch_bounds__(512) void k_scan_blk() {
    __shared__ int sm[512];
    int t = threadIdx.x;
    int v = (t < NSCANB) ? g_bsum[t] : 0;
    int x = v;
    sm[t] = x; __syncthreads();
#pragma unroll
    for (int off = 1; off < 512; off <<= 1) {
        int y = (t >= off) ? sm[t - off] : 0;
        __syncthreads();
        x += y; sm[t] = x;
        __syncthreads();
    }
    if (t < NSCANB) g_bsum[t] = x - v;   // exclusive
}

__global__ void k_scatter(const int* __restrict__ ei,
                          const int* __restrict__ et) {
    int e = blockIdx.x * blockDim.x + threadIdx.x;
    if (e >= N_EDGES) return;
    int s = ei[e];
    int d = ei[N_EDGES + e];
    int t = et[e];
    int pos = g_histL[s] + g_bsum[s >> 8] + atomicAdd(&g_cursor[s], 1);
    g_es[pos] = s; g_ed[pos] = d; g_et[pos] = t;
}

// fused weight [w_sl | B0..B3] -> bf16 hi/lo u32 k-pairs, layout [l][n][k2]
__global__ void k_wcat(const float* __restrict__ w_sl,
                       const float* __restrict__ bases) {
    int idx = blockIdx.x * blockDim.x + threadIdx.x;
    int total = 2 * NCOLS * 64;
    if (idx >= total) return;
    int l   = idx / (NCOLS * 64);
    int rem = idx - l * (NCOLS * 64);
    int n   = rem >> 6;
    int k2  = rem & 63;
    float v0, v1;
    if (n < DIM) {
        v0 = w_sl[l * DIM * DIM + (2 * k2) * DIM + n];
        v1 = w_sl[l * DIM * DIM + (2 * k2 + 1) * DIM + n];
    } else {
        int b = (n - DIM) >> 7;
        int f = (n - DIM) & 127;
        const float* bp = bases + l * N_BASES * DIM * DIM + b * DIM * DIM;
        v0 = bp[(2 * k2) * DIM + f];
        v1 = bp[(2 * k2 + 1) * DIM + f];
    }
    __nv_bfloat16 h0 = __float2bfloat16(v0);
    __nv_bfloat16 h1 = __float2bfloat16(v1);
    __nv_bfloat16 l0 = __float2bfloat16(v0 - __bfloat162float(h0));
    __nv_bfloat16 l1 = __float2bfloat16(v1 - __bfloat162float(h1));
    __nv_bfloat162 ph(h0, h1), pl(l0, l1);
    g_W32h[idx] = *reinterpret_cast<unsigned*>(&ph);
    g_W32l[idx] = *reinterpret_cast<unsigned*>(&pl);
}

__global__ void k_zero_stats() {
    int t = threadIdx.x;
    if (t < DIM) { g_sum[t] = 0.0f; g_sumsq[t] = 0.0f; }
}

// ---------------- tensor-core GEMM helpers --------------------------------
__device__ __forceinline__ void mma16816(float* c, const unsigned* a,
                                         const unsigned* b) {
    asm volatile(
        "mma.sync.aligned.m16n8k16.row.col.f32.bf16.bf16.f32 "
        "{%0,%1,%2,%3}, {%4,%5,%6,%7}, {%8,%9}, {%0,%1,%2,%3};\n"
        : "+f"(c[0]), "+f"(c[1]), "+f"(c[2]), "+f"(c[3])
        : "r"(a[0]), "r"(a[1]), "r"(a[2]), "r"(a[3]), "r"(b[0]), "r"(b[1]));
}

__device__ __forceinline__ void ldsm4(unsigned* r, const void* p) {
    unsigned addr = (unsigned)__cvta_generic_to_shared(p);
    asm volatile(
        "ldmatrix.sync.aligned.m8n8.x4.shared.b16 {%0,%1,%2,%3}, [%4];"
        : "=r"(r[0]), "=r"(r[1]), "=r"(r[2]), "=r"(r[3]) : "r"(addr));
}

__device__ __forceinline__ void cp16(void* dst_smem, const void* src) {
    unsigned d = (unsigned)__cvta_generic_to_shared(dst_smem);
    asm volatile("cp.async.cg.shared.global [%0], [%1], 16;\n"
                 :: "r"(d), "l"(src));
}

// prefetch one full-K W tile (2h x 128n x 64k2 u32) into a ws buffer
__device__ __forceinline__ void prefetch_w(unsigned* wsbuf, int layer,
                                           int n0, int tid) {
#pragma unroll
    for (int i = 0; i < 8; i++) {
        int lin = tid + i * 512;            // 0..4095 float4
        int h   = lin >> 11;
        int rem = lin & 2047;
        int n   = rem >> 4;
        int q   = rem & 15;                 // float4 index (k2 = q*4)
        const unsigned* src = (h ? g_W32l : g_W32h) +
                              (layer * NCOLS + n0 + n) * 64 + q * 4;
        cp16(&wsbuf[(h * 128 + n) * WS_STRIDE + q * 4], src);
    }
}

// ---------------- tensor-core GEMM: Z = x @ Wcat (bf16x3 split) -----------
__global__ __launch_bounds__(512) void k_gemm_tc(int layer,
                                                 const float* __restrict__ xext,
                                                 const float* __restrict__ b_sl,
                                                 int bnflag) {
    extern __shared__ unsigned char smraw[];
    __nv_bfloat16* xs = reinterpret_cast<__nv_bfloat16*>(smraw);
    unsigned* ws = reinterpret_cast<unsigned*>(smraw + SMEM_XS);

    const float* __restrict__ xsrc = bnflag ? g_out0 : xext;
    float* __restrict__ outbuf = bnflag ? g_out1 : g_out0;

    int tid  = threadIdx.x;
    int lane = tid & 31;
    int wid  = tid >> 5;
    int g    = lane >> 2;
    int tig  = lane & 3;
    int m_base = (wid & 3) * 32;
    int n_base = (wid >> 2) * 32;
    int m0 = blockIdx.x * 128;

    // kick off W prefetch for n-tiles 0 and 1 (overlaps the x load below)
    prefetch_w(ws, layer, 0, tid);
    asm volatile("cp.async.commit_group;\n" ::: "memory");
    prefetch_w(ws + WSBUF_U32, layer, 128, tid);
    asm volatile("cp.async.commit_group;\n" ::: "memory");

    // ---- load x tile (128 x 128) ONCE, BN+ReLU opt, split hi/lo ----
#pragma unroll
    for (int i = 0; i < 8; i++) {
        int lin = tid + i * 512;
        int row = lin >> 5;
        int q   = lin & 31;
        int c0  = q * 4;
        float4 v = make_float4(0.f, 0.f, 0.f, 0.f);
        if (m0 + row < N_ENT) {
            v = *reinterpret_cast<const float4*>(&xsrc[(m0 + row) * DIM + c0]);
            if (bnflag) {
                float invd = 1.0f / fmaxf(g_deg[m0 + row], 1.0f);
                float4 sc = *reinterpret_cast<const float4*>(&g_scale[c0]);
                float4 sh = *reinterpret_cast<const float4*>(&g_shift[c0]);
                v.x = fmaxf(fmaf(v.x * invd, sc.x, sh.x), 0.f);
                v.y = fmaxf(fmaf(v.y * invd, sc.y, sh.y), 0.f);
                v.z = fmaxf(fmaf(v.z * invd, sc.z, sh.z), 0.f);
                v.w = fmaxf(fmaf(v.w * invd, sc.w, sh.w), 0.f);
            }
        }
        __nv_bfloat16 h0 = __float2bfloat16(v.x);
        __nv_bfloat16 h1 = __float2bfloat16(v.y);
        __nv_bfloat16 h2 = __float2bfloat16(v.z);
        __nv_bfloat16 h3 = __float2bfloat16(v.w);
        __nv_bfloat16 l0 = __float2bfloat16(v.x - __bfloat162float(h0));
        __nv_bfloat16 l1 = __float2bfloat16(v.y - __bfloat162float(h1));
        __nv_bfloat16 l2 = __float2bfloat16(v.z - __bfloat162float(h2));
        __nv_bfloat16 l3 = __float2bfloat16(v.w - __bfloat162float(h3));
        __nv_bfloat16* xh = &xs[row * XS_STRIDE + c0];
        __nv_bfloat16* xl = &xs[(128 + row) * XS_STRIDE + c0];
        *reinterpret_cast<__nv_bfloat162*>(xh)     = __nv_bfloat162(h0, h1);
        *reinterpret_cast<__nv_bfloat162*>(xh + 2) = __nv_bfloat162(h2, h3);
        *reinterpret_cast<__nv_bfloat162*>(xl)     = __nv_bfloat162(l0, l1);
        *reinterpret_cast<__nv_bfloat162*>(xl + 2) = __nv_bfloat162(l2, l3);
    }

    int a_row = m_base + (lane & 15);
    int a_colsel = (lane >> 4) << 3;
    int b_row = n_base + (lane & 7) + ((lane & 16) ? 8 : 0);
    int b_ksel = (lane & 8) ? 4 : 0;

    const float* __restrict__ bias = b_sl + layer * DIM;

    for (int ntile = 0; ntile < 5; ntile++) {
        unsigned* wscur = ws + (ntile & 1) * WSBUF_U32;
        if (ntile < 4)
            asm volatile("cp.async.wait_group 1;\n" ::: "memory");
        else
            asm volatile("cp.async.wait_group 0;\n" ::: "memory");
        __syncthreads();   // W tile visible to all; xs ready (ntile 0)

        float C[2][4][4];
#pragma unroll
        for (int mt = 0; mt < 2; mt++)
#pragma unroll
            for (int nt = 0; nt < 4; nt++)
#pragma unroll
                for (int j = 0; j < 4; j++) C[mt][nt][j] = 0.0f;

#pragma unroll
        for (int kc = 0; kc < 4; kc++) {
#pragma unroll
            for (int s = 0; s < 2; s++) {
                unsigned A[2][2][4];
#pragma unroll
                for (int h = 0; h < 2; h++)
#pragma unroll
                    for (int mt = 0; mt < 2; mt++)
                        ldsm4(A[h][mt],
                              &xs[(h * 128 + a_row + mt * 16) * XS_STRIDE +
                                  kc * 32 + s * 16 + a_colsel]);
                unsigned B[2][2][4];
#pragma unroll
                for (int h = 0; h < 2; h++)
#pragma unroll
                    for (int nt2 = 0; nt2 < 2; nt2++)
                        ldsm4(B[h][nt2],
                              &wscur[(h * 128 + b_row + nt2 * 16) * WS_STRIDE +
                                     kc * 16 + s * 8 + b_ksel]);
#pragma unroll
                for (int mt = 0; mt < 2; mt++)
#pragma unroll
                    for (int nt = 0; nt < 4; nt++) {
                        const unsigned* bh = &B[0][nt >> 1][(nt & 1) * 2];
                        const unsigned* bl = &B[1][nt >> 1][(nt & 1) * 2];
                        mma16816(C[mt][nt], A[0][mt], bh);
                        mma16816(C[mt][nt], A[0][mt], bl);
                        mma16816(C[mt][nt], A[1][mt], bh);
                    }
            }
        }

        // ---- epilogue for this n-tile ----
        int n0 = ntile * 128;
        bool isOut = (ntile == 0);
#pragma unroll
        for (int mt = 0; mt < 2; mt++) {
#pragma unroll
            for (int nt = 0; nt < 4; nt++) {
                int col  = n_base + nt * 8 + tig * 2;
                int row0 = m0 + m_base + mt * 16 + g;
                float b0 = 0.f, b1 = 0.f;
                if (isOut) { b0 = bias[col]; b1 = bias[col + 1]; }
                float2 v0 = make_float2(C[mt][nt][0] + b0, C[mt][nt][1] + b1);
                float2 v1 = make_float2(C[mt][nt][2] + b0, C[mt][nt][3] + b1);
                if (isOut) {
                    if (row0 < N_ENT)
                        *reinterpret_cast<float2*>(&outbuf[row0 * DIM + col]) = v0;
                    if (row0 + 8 < N_ENT)
                        *reinterpret_cast<float2*>(&outbuf[(row0 + 8) * DIM + col]) = v1;
                } else {
                    int yc = n0 - DIM + col;
                    if (row0 < N_ENT)
                        *reinterpret_cast<float2*>(&g_Y[row0 * 512 + yc]) = v0;
                    if (row0 + 8 < N_ENT)
                        *reinterpret_cast<float2*>(&g_Y[(row0 + 8) * 512 + yc]) = v1;
                }
            }
        }

        __syncthreads();   // all warps done reading wscur before its reuse
        if (ntile + 2 < 5) {
            prefetch_w(wscur, layer, (ntile + 2) * 128, tid);
            asm volatile("cp.async.commit_group;\n" ::: "memory");
        }
    }
}

// ---------------- edge kernel (src-sorted): one warp per edge -------------
__global__ __launch_bounds__(256) void k_edge_s(const float* __restrict__ coeff,
                                                int outsel) {
    float* __restrict__ outbuf = outsel ? g_out1 : g_out0;
    int warp = (blockIdx.x * blockDim.x + threadIdx.x) >> 5;
    int lane = threadIdx.x & 31;
    if (warp >= N_EDGES) return;

    int s = g_es[warp];
    int d = g_ed[warp];
    int t = g_et[warp];

    float4 c = *reinterpret_cast<const float4*>(&coeff[t * 4]);
    const float4* __restrict__ yr =
        reinterpret_cast<const float4*>(&g_Y[s * 512]) + lane;
    float4 y0 = yr[0], y1 = yr[32], y2 = yr[64], y3 = yr[96];

    float4 m;
    m.x = c.x * y0.x + c.y * y1.x + c.z * y2.x + c.w * y3.x;
    m.y = c.x * y0.y + c.y * y1.y + c.z * y2.y + c.w * y3.y;
    m.z = c.x * y0.z + c.y * y1.z + c.z * y2.z + c.w * y3.z;
    m.w = c.x * y0.w + c.y * y1.w + c.z * y2.w + c.w * y3.w;

    atomicAdd(reinterpret_cast<float4*>(&outbuf[d * DIM + lane * 4]), m);
}

// ---------------- BN stats ------------------------------------------------
__global__ __launch_bounds__(256) void k_bn_stats(int outsel) {
    const float* __restrict__ outbuf = outsel ? g_out1 : g_out0;
    int tid  = threadIdx.x;
    int c4   = tid & 31;
    int rsub = tid >> 5;
    int r0   = blockIdx.x * 1024;
    float4 s = make_float4(0.f, 0.f, 0.f, 0.f);
    float4 q = make_float4(0.f, 0.f, 0.f, 0.f);
    for (int i = 0; i < 128; i++) {
        int r = r0 + rsub + i * 8;
        if (r < N_ENT) {
            float invd = 1.0f / fmaxf(g_deg[r], 1.0f);
            float4 v = *reinterpret_cast<const float4*>(&outbuf[r * DIM + c4 * 4]);
            v.x *= invd; v.y *= invd; v.z *= invd; v.w *= invd;
            s.x += v.x; s.y += v.y; s.z += v.z; s.w += v.w;
            q.x += v.x * v.x; q.y += v.y * v.y;
            q.z += v.z * v.z; q.w += v.w * v.w;
        }
    }
    atomicAdd(&g_sum[c4 * 4 + 0], s.x);
    atomicAdd(&g_sum[c4 * 4 + 1], s.y);
    atomicAdd(&g_sum[c4 * 4 + 2], s.z);
    atomicAdd(&g_sum[c4 * 4 + 3], s.w);
    atomicAdd(&g_sumsq[c4 * 4 + 0], q.x);
    atomicAdd(&g_sumsq[c4 * 4 + 1], q.y);
    atomicAdd(&g_sumsq[c4 * 4 + 2], q.z);
    atomicAdd(&g_sumsq[c4 * 4 + 3], q.w);
}

// ---------------- BN finalize ---------------------------------------------
__global__ void k_bn_final(int layer, const float* __restrict__ gamma,
                           const float* __restrict__ beta) {
    int c = threadIdx.x;
    if (c >= DIM) return;
    const float INV_N = 1.0f / (float)N_ENT;
    float mu  = g_sum[c] * INV_N;
    float var = g_sumsq[c] * INV_N - mu * mu;
    float rs  = rsqrtf(var + BN_EPS);
    float sc  = rs * gamma[layer * DIM + c];
    g_scale[c] = sc;
    g_shift[c] = beta[layer * DIM + c] - mu * sc;
}

// ---------------- scoring -------------------------------------------------
__device__ __forceinline__ float4 bnrelu4(float4 v, float invd,
                                          float4 sc, float4 sh) {
    v.x = fmaxf(fmaf(v.x * invd, sc.x, sh.x), 0.f);
    v.y = fmaxf(fmaf(v.y * invd, sc.y, sh.y), 0.f);
    v.z = fmaxf(fmaf(v.z * invd, sc.z, sh.z), 0.f);
    v.w = fmaxf(fmaf(v.w * invd, sc.w, sh.w), 0.f);
    return v;
}

__global__ __launch_bounds__(256) void k_score(const int* __restrict__ head,
                                               const int* __restrict__ relidx,
                                               const int* __restrict__ tail,
                                               const int* __restrict__ neg,
                                               const float* __restrict__ rel_tab,
                                               float* __restrict__ out) {
    __shared__ float hr[DIM];
    int b = blockIdx.x;
    int tid = threadIdx.x;
    int h = head[b], r = relidx[b], t = tail[b];
    if (tid < DIM) {
        float invd = 1.0f / fmaxf(g_deg[h], 1.0f);
        float v = g_out1[h * DIM + tid];
        v = fmaxf(fmaf(v * invd, g_scale[tid], g_shift[tid]), 0.f);
        hr[tid] = v + rel_tab[r * DIM + tid];
    }
    __syncthreads();

    int wid = tid >> 5, lane = tid & 31;
    float4 hv = reinterpret_cast<const float4*>(hr)[lane];
    float4 sc = *reinterpret_cast<const float4*>(&g_scale[lane * 4]);
    float4 sh = *reinterpret_cast<const float4*>(&g_shift[lane * 4]);

    for (int j = wid; j < 1 + N_NEG; j += 8) {
        int target = (j == 0) ? t : neg[b * N_NEG + (j - 1)];
        float invd = 1.0f / fmaxf(g_deg[target], 1.0f);
        float4 ev = reinterpret_cast<const float4*>(&g_out1[target * DIM])[lane];
        ev = bnrelu4(ev, invd, sc, sh);
        float dx = hv.x - ev.x, dy = hv.y - ev.y,
              dz = hv.z - ev.z, dw = hv.w - ev.w;
        float sum = dx * dx + dy * dy + dz * dz + dw * dw;
#pragma unroll
        for (int off = 16; off > 0; off >>= 1)
            sum += __shfl_xor_sync(0xffffffffu, sum, off);
        if (lane == 0) {
            float scv = -sqrtf(sum);
            if (j == 0) out[b] = scv;
            else        out[BATCH + b * N_NEG + (j - 1)] = scv;
        }
    }
}

// ---------------- launcher ------------------------------------------------
extern "C" void kernel_launch(void* const* d_in, const int* in_sizes, int n_in,
                              void* d_out, int out_size) {
    const int*   head    = (const int*)d_in[0];
    const int*   relidx  = (const int*)d_in[1];
    const int*   tail    = (const int*)d_in[2];
    const int*   neg     = (const int*)d_in[3];
    const int*   ei      = (const int*)d_in[4];
    const int*   et      = (const int*)d_in[5];
    const float* ent_tab = (const float*)d_in[6];
    const float* rel_tab = (const float*)d_in[7];
    const float* bases   = (const float*)d_in[8];
    const float* coeffs  = (const float*)d_in[9];
    const float* w_sl    = (const float*)d_in[10];
    const float* b_sl    = (const float*)d_in[11];
    const float* gamma   = (const float*)d_in[12];
    const float* beta    = (const float*)d_in[13];
    float* out = (float*)d_out;

    cudaFuncSetAttribute(k_gemm_tc,
                         cudaFuncAttributeMaxDynamicSharedMemorySize, SMEM_GEMM);

    int ggrid = (N_ENT + 127) / 128;

    // launch #4 = layer-0 GEMM (so ncu -s5-c1 profiles it)
    k_zero_all<<<(N_ENT + 255) / 256, 256>>>();                    // 1
    k_deg_hist<<<(N_EDGES + 255) / 256, 256>>>(ei);                // 2
    k_wcat<<<(2 * NCOLS * 64 + 255) / 256, 256>>>(w_sl, bases);    // 3
    k_gemm_tc<<<ggrid, 512, SMEM_GEMM>>>(0, ent_tab, b_sl, 0);     // 4
    // edge sort (independent of gemm)
    k_scan_part<<<NSCANB, 256>>>();                                // 5
    k_scan_blk<<<1, 512>>>();                                      // 6
    k_scatter<<<(N_EDGES + 255) / 256, 256>>>(ei, et);             // 7

    // layer 0 rest
    k_edge_s<<<(N_EDGES * 32 + 255) / 256, 256>>>(coeffs, 0);
    k_zero_stats<<<1, 128>>>();
    k_bn_stats<<<(N_ENT + 1023) / 1024, 256>>>(0);
    k_bn_final<<<1, 128>>>(0, gamma, beta);

    // layer 1
    k_gemm_tc<<<ggrid, 512, SMEM_GEMM>>>(1, ent_tab, b_sl, 1);
    k_edge_s<<<(N_EDGES * 32 + 255) / 256, 256>>>(coeffs + N_REL * N_BASES, 1);
    k_zero_stats<<<1, 128>>>();
    k_bn_stats<<<(N_ENT + 1023) / 1024, 256>>>(1);
    k_bn_final<<<1, 128>>>(1, gamma, beta);

    // scoring with fused BN on gathered rows
    k_score<<<BATCH, 256>>>(head, relidx, tail, neg, rel_tab, out);
}

// round 9
// speedup vs baseline: 1.8275x; 1.0022x over previous
#include <cuda_runtime.h>
#include <cuda_bf16.h>
#include <math.h>

#define N_ENT    100000
#define N_REL    16
#define DIM      128
#define N_BASES  4
#define N_EDGES  640000
#define BATCH    1024
#define N_NEG    64
#define KTOT     640          // 128 (x/self) + 512 (agg/bases)
#define BN_EPS   1e-5f
#define NSCANB   391          // ceil(N_ENT/256)

// GEMM smem geometry (K-chunk = 64, N = 128 fixed)
#define A_STRIDE 72                       // bf16 per A row (144 B, ldsm clean)
#define ABUF_ELEM (2 * 128 * A_STRIDE)    // bf16 per A buffer (hi+lo planes)
#define W_STRIDE 36                       // u32 per W row (144 B, ldsm clean)
#define WBUF_U32 (2 * 128 * W_STRIDE)
#define SMEM_A  (2 * ABUF_ELEM * 2)       // 73728 B (double buffered)
#define SMEM_W  (2 * WBUF_U32 * 4)        // 73728 B (double buffered)
#define SMEM_G  (SMEM_A + SMEM_W)         // 147456 B

// ---------------- device scratch (static) ---------------------------------
__device__ float g_out0[N_ENT * DIM];
__device__ float g_out1[N_ENT * DIM];
__device__ __nv_bfloat16 g_aggh[N_ENT * 512];   // aggregated msgs, bf16 hi
__device__ __nv_bfloat16 g_aggl[N_ENT * 512];   // bf16 lo residual
__device__ float g_sum[DIM];
__device__ float g_sumsq[DIM];
__device__ float g_scale[DIM];
__device__ float g_shift[DIM];
// counting sort of edges by DST; g_hist doubles as deg
__device__ int g_hist[N_ENT];
__device__ int g_histL[N_ENT];
__device__ int g_bsum[NSCANB];
__device__ int g_cursor[N_ENT];
__device__ int g_total;
__device__ int g_es[N_EDGES];             // sorted-by-dst: src
__device__ int g_et[N_EDGES];             // sorted-by-dst: type
// Wfull = [w_sl ; B0..B3]  (640 x 128), bf16 hi/lo u32 k-pairs,
// layout [l][n][k2]: idx = (l*128 + n)*320 + k2
__device__ unsigned g_W32h[2 * 128 * 320];
__device__ unsigned g_W32l[2 * 128 * 320];

// ---------------- setup ---------------------------------------------------
__global__ void k_zero_all() {
    int i = blockIdx.x * blockDim.x + threadIdx.x;
    if (i < N_ENT) { g_hist[i] = 0; g_cursor[i] = 0; }
    if (i == 0) g_total = 0;
}

__global__ void k_hist(const int* __restrict__ ei) {
    int e = blockIdx.x * blockDim.x + threadIdx.x;
    if (e < N_EDGES) atomicAdd(&g_hist[ei[N_EDGES + e]], 1);
}

// per-block scan + atomic global offset (order across blocks irrelevant)
__global__ __launch_bounds__(256) void k_scan_part() {
    __shared__ int sm[256];
    int t = threadIdx.x;
    int idx = blockIdx.x * 256 + t;
    int v = (idx < N_ENT) ? g_hist[idx] : 0;
    int x = v;
    sm[t] = x; __syncthreads();
#pragma unroll
    for (int off = 1; off < 256; off <<= 1) {
        int y = (t >= off) ? sm[t - off] : 0;
        __syncthreads();
        x += y; sm[t] = x;
        __syncthreads();
    }
    if (idx < N_ENT) g_histL[idx] = x - v;
    if (t == 255) g_bsum[blockIdx.x] = atomicAdd(&g_total, x);
}

__global__ void k_scatter(const int* __restrict__ ei,
                          const int* __restrict__ et) {
    int e = blockIdx.x * blockDim.x + threadIdx.x;
    if (e >= N_EDGES) return;
    int s = ei[e];
    int d = ei[N_EDGES + e];
    int pos = g_histL[d] + g_bsum[d >> 8] + atomicAdd(&g_cursor[d], 1);
    g_es[pos] = s; g_et[pos] = et[e];
}

// Wfull rows: k<128 -> w_sl[k][n];  k>=128 -> bases[b][kr][n]
__global__ void k_wcat(const float* __restrict__ w_sl,
                       const float* __restrict__ bases) {
    int idx = blockIdx.x * blockDim.x + threadIdx.x;
    int total = 2 * 128 * 320;
    if (idx >= total) return;
    int l   = idx / (128 * 320);
    int rem = idx - l * (128 * 320);
    int n   = rem / 320;
    int k2  = rem - n * 320;
    int k   = 2 * k2;
    float v0, v1;
    if (k < DIM) {
        v0 = w_sl[l * DIM * DIM + k * DIM + n];
        v1 = w_sl[l * DIM * DIM + (k + 1) * DIM + n];
    } else {
        int kk = k - DIM;
        int b = kk >> 7;
        int kr = kk & 127;
        const float* bp = bases + (l * N_BASES + b) * DIM * DIM;
        v0 = bp[kr * DIM + n];
        v1 = bp[(kr + 1) * DIM + n];
    }
    __nv_bfloat16 h0 = __float2bfloat16(v0);
    __nv_bfloat16 h1 = __float2bfloat16(v1);
    __nv_bfloat16 l0 = __float2bfloat16(v0 - __bfloat162float(h0));
    __nv_bfloat16 l1 = __float2bfloat16(v1 - __bfloat162float(h1));
    __nv_bfloat162 ph(h0, h1), pl(l0, l1);
    g_W32h[idx] = *reinterpret_cast<unsigned*>(&ph);
    g_W32l[idx] = *reinterpret_cast<unsigned*>(&pl);
}

__global__ void k_zero_stats() {
    int t = threadIdx.x;
    if (t < DIM) { g_sum[t] = 0.0f; g_sumsq[t] = 0.0f; }
}

// ---------------- helpers -------------------------------------------------
__device__ __forceinline__ float4 bnrelu4(float4 v, float invd,
                                          float4 sc, float4 sh) {
    v.x = fmaxf(fmaf(v.x * invd, sc.x, sh.x), 0.f);
    v.y = fmaxf(fmaf(v.y * invd, sc.y, sh.y), 0.f);
    v.z = fmaxf(fmaf(v.z * invd, sc.z, sh.z), 0.f);
    v.w = fmaxf(fmaf(v.w * invd, sc.w, sh.w), 0.f);
    return v;
}

__device__ __forceinline__ void mma16816(float* c, const unsigned* a,
                                         const unsigned* b) {
    asm volatile(
        "mma.sync.aligned.m16n8k16.row.col.f32.bf16.bf16.f32 "
        "{%0,%1,%2,%3}, {%4,%5,%6,%7}, {%8,%9}, {%0,%1,%2,%3};\n"
        : "+f"(c[0]), "+f"(c[1]), "+f"(c[2]), "+f"(c[3])
        : "r"(a[0]), "r"(a[1]), "r"(a[2]), "r"(a[3]), "r"(b[0]), "r"(b[1]));
}

__device__ __forceinline__ void ldsm4(unsigned* r, const void* p) {
    unsigned addr = (unsigned)__cvta_generic_to_shared(p);
    asm volatile(
        "ldmatrix.sync.aligned.m8n8.x4.shared.b16 {%0,%1,%2,%3}, [%4];"
        : "=r"(r[0]), "=r"(r[1]), "=r"(r[2]), "=r"(r[3]) : "r"(addr));
}

__device__ __forceinline__ void cp16(void* dst_smem, const void* src) {
    unsigned d = (unsigned)__cvta_generic_to_shared(dst_smem);
    asm volatile("cp.async.cg.shared.global [%0], [%1], 16;\n"
                 :: "r"(d), "l"(src));
}

// ---------------- edge aggregation (dst-sorted, warp per dst) -------------
// agg[d, b*128+j] = sum_{e->d} coeff[t_e, b] * x[s_e, j]; stored bf16 hi/lo.
__global__ __launch_bounds__(256) void k_edge_agg(const float* __restrict__ coeff,
                                                  const float* __restrict__ xext,
                                                  int bnflag) {
    __shared__ float csm[N_REL * 4];
    int tid = threadIdx.x;
    if (tid < N_REL * 4) csm[tid] = coeff[tid];
    __syncthreads();

    int d    = blockIdx.x * 8 + (tid >> 5);
    int lane = tid & 31;
    if (d >= N_ENT) return;

    int start = g_histL[d] + g_bsum[d >> 8];
    int cnt   = g_hist[d];
    const float* __restrict__ xsrc = bnflag ? g_out0 : xext;

    float4 sc, sh;
    if (bnflag) {
        sc = *reinterpret_cast<const float4*>(&g_scale[lane * 4]);
        sh = *reinterpret_cast<const float4*>(&g_shift[lane * 4]);
    }

    float4 a0 = make_float4(0.f, 0.f, 0.f, 0.f);
    float4 a1 = a0, a2 = a0, a3 = a0;

    for (int e = start; e < start + cnt; e++) {
        int s = g_es[e];
        int t = g_et[e];
        float4 c = *reinterpret_cast<const float4*>(&csm[t * 4]);
        float4 xv = *reinterpret_cast<const float4*>(&xsrc[s * DIM + lane * 4]);
        if (bnflag) {
            float invd = 1.0f / fmaxf((float)g_hist[s], 1.0f);
            xv = bnrelu4(xv, invd, sc, sh);
        }
        a0.x = fmaf(c.x, xv.x, a0.x); a0.y = fmaf(c.x, xv.y, a0.y);
        a0.z = fmaf(c.x, xv.z, a0.z); a0.w = fmaf(c.x, xv.w, a0.w);
        a1.x = fmaf(c.y, xv.x, a1.x); a1.y = fmaf(c.y, xv.y, a1.y);
        a1.z = fmaf(c.y, xv.z, a1.z); a1.w = fmaf(c.y, xv.w, a1.w);
        a2.x = fmaf(c.z, xv.x, a2.x); a2.y = fmaf(c.z, xv.y, a2.y);
        a2.z = fmaf(c.z, xv.z, a2.z); a2.w = fmaf(c.z, xv.w, a2.w);
        a3.x = fmaf(c.w, xv.x, a3.x); a3.y = fmaf(c.w, xv.y, a3.y);
        a3.z = fmaf(c.w, xv.z, a3.z); a3.w = fmaf(c.w, xv.w, a3.w);
    }

    float4 acc[4] = {a0, a1, a2, a3};
#pragma unroll
    for (int b = 0; b < 4; b++) {
        float4 a = acc[b];
        __nv_bfloat16 hx = __float2bfloat16(a.x);
        __nv_bfloat16 hy = __float2bfloat16(a.y);
        __nv_bfloat16 hz = __float2bfloat16(a.z);
        __nv_bfloat16 hw = __float2bfloat16(a.w);
        __nv_bfloat16 lx = __float2bfloat16(a.x - __bfloat162float(hx));
        __nv_bfloat16 ly = __float2bfloat16(a.y - __bfloat162float(hy));
        __nv_bfloat16 lz = __float2bfloat16(a.z - __bfloat162float(hz));
        __nv_bfloat16 lw = __float2bfloat16(a.w - __bfloat162float(hw));
        __nv_bfloat162 hp0(hx, hy), hp1(hz, hw), lp0(lx, ly), lp1(lz, lw);
        int off = d * 512 + b * 128 + lane * 4;
        uint2 hv = make_uint2(*reinterpret_cast<unsigned*>(&hp0),
                              *reinterpret_cast<unsigned*>(&hp1));
        uint2 lv = make_uint2(*reinterpret_cast<unsigned*>(&lp0),
                              *reinterpret_cast<unsigned*>(&lp1));
        *reinterpret_cast<uint2*>(&g_aggh[off]) = hv;
        *reinterpret_cast<uint2*>(&g_aggl[off]) = lv;
    }
}

// ---------------- GEMM: out = [x | agg] @ Wfull + bias  (K=640, N=128) ----
__device__ __forceinline__ void prefetch_w2(unsigned* wbuf, int layer,
                                            int kc, int tid) {
#pragma unroll
    for (int i = 0; i < 4; i++) {
        int lin = tid + i * 512;          // 0..2047
        int h   = lin >> 10;
        int rem = lin & 1023;
        int n   = rem >> 3;
        int q   = rem & 7;
        const unsigned* src = (h ? g_W32l : g_W32h) +
                              (layer * 128 + n) * 320 + kc * 32 + q * 4;
        cp16(&wbuf[(h * 128 + n) * W_STRIDE + q * 4], src);
    }
}

__device__ __forceinline__ void prefetch_a2(__nv_bfloat16* abuf, int m0,
                                            int kc, int tid) {
    int aggc = kc * 64 - 128;             // kc >= 2 always
#pragma unroll
    for (int i = 0; i < 4; i++) {
        int lin = tid + i * 512;
        int h   = lin >> 10;
        int rem = lin & 1023;
        int row = rem >> 3;
        int q   = rem & 7;
        int r = m0 + row; if (r >= N_ENT) r = N_ENT - 1;
        const __nv_bfloat16* src = (h ? g_aggl : g_aggh) +
                                   r * 512 + aggc + q * 8;
        cp16(&abuf[(h * 128 + row) * A_STRIDE + q * 8], src);
    }
}

__global__ __launch_bounds__(512) void k_gemm2(int layer,
                                               const float* __restrict__ xext,
                                               const float* __restrict__ b_sl,
                                               int bnflag) {
    extern __shared__ unsigned char smraw[];
    __nv_bfloat16* ab = reinterpret_cast<__nv_bfloat16*>(smraw);       // 2 bufs
    unsigned* wb = reinterpret_cast<unsigned*>(smraw + SMEM_A);        // 2 bufs

    const float* __restrict__ xsrc = bnflag ? g_out0 : xext;
    float* __restrict__ outbuf = bnflag ? g_out1 : g_out0;

    int tid  = threadIdx.x;
    int lane = tid & 31;
    int wid  = tid >> 5;
    int g    = lane >> 2;
    int tig  = lane & 3;
    int m_base = (wid & 3) * 32;
    int n_base = (wid >> 2) * 32;
    int m0 = blockIdx.x * 128;

    // prefetch W chunks 0,1
    prefetch_w2(wb, layer, 0, tid);
    asm volatile("cp.async.commit_group;\n" ::: "memory");
    prefetch_w2(wb + WBUF_U32, layer, 1, tid);
    asm volatile("cp.async.commit_group;\n" ::: "memory");

    // x part (K 0..127) -> A buffers 0 and 1, BN+ReLU opt, split hi/lo
#pragma unroll
    for (int i = 0; i < 8; i++) {
        int lin = tid + i * 512;
        int row = lin >> 5;
        int q   = lin & 31;
        int c0  = q * 4;
        float4 v = make_float4(0.f, 0.f, 0.f, 0.f);
        if (m0 + row < N_ENT) {
            v = *reinterpret_cast<const float4*>(&xsrc[(m0 + row) * DIM + c0]);
            if (bnflag) {
                float invd = 1.0f / fmaxf((float)g_hist[m0 + row], 1.0f);
                float4 sc = *reinterpret_cast<const float4*>(&g_scale[c0]);
                float4 sh = *reinterpret_cast<const float4*>(&g_shift[c0]);
                v = bnrelu4(v, invd, sc, sh);
            }
        }
        __nv_bfloat16 h0 = __float2bfloat16(v.x);
        __nv_bfloat16 h1 = __float2bfloat16(v.y);
        __nv_bfloat16 h2 = __float2bfloat16(v.z);
        __nv_bfloat16 h3 = __float2bfloat16(v.w);
        __nv_bfloat16 l0 = __float2bfloat16(v.x - __bfloat162float(h0));
        __nv_bfloat16 l1 = __float2bfloat16(v.y - __bfloat162float(h1));
        __nv_bfloat16 l2 = __float2bfloat16(v.z - __bfloat162float(h2));
        __nv_bfloat16 l3 = __float2bfloat16(v.w - __bfloat162float(h3));
        int buf = c0 >> 6;
        int kl  = c0 & 63;
        __nv_bfloat16* dsth = ab + buf * ABUF_ELEM + row * A_STRIDE + kl;
        __nv_bfloat16* dstl = dsth + 128 * A_STRIDE;
        *reinterpret_cast<__nv_bfloat162*>(dsth)     = __nv_bfloat162(h0, h1);
        *reinterpret_cast<__nv_bfloat162*>(dsth + 2) = __nv_bfloat162(h2, h3);
        *reinterpret_cast<__nv_bfloat162*>(dstl)     = __nv_bfloat162(l0, l1);
        *reinterpret_cast<__nv_bfloat162*>(dstl + 2) = __nv_bfloat162(l2, l3);
    }

    int a_row = m_base + (lane & 15);
    int a_colsel = (lane >> 4) << 3;
    int b_row = n_base + (lane & 7) + ((lane & 16) ? 8 : 0);
    int b_ksel = (lane & 8) ? 4 : 0;

    float C[2][4][4];
#pragma unroll
    for (int mt = 0; mt < 2; mt++)
#pragma unroll
        for (int nt = 0; nt < 4; nt++)
#pragma unroll
            for (int j = 0; j < 4; j++) C[mt][nt][j] = 0.0f;

    for (int kc = 0; kc < 10; kc++) {
        if (kc < 9)
            asm volatile("cp.async.wait_group 1;\n" ::: "memory");
        else
            asm volatile("cp.async.wait_group 0;\n" ::: "memory");
        __syncthreads();

        __nv_bfloat16* acur = ab + (kc & 1) * ABUF_ELEM;
        unsigned* wcur = wb + (kc & 1) * WBUF_U32;

#pragma unroll
        for (int s = 0; s < 4; s++) {
            unsigned A[2][2][4];
#pragma unroll
            for (int h = 0; h < 2; h++)
#pragma unroll
                for (int mt = 0; mt < 2; mt++)
                    ldsm4(A[h][mt],
                          &acur[(h * 128 + a_row + mt * 16) * A_STRIDE +
                                s * 16 + a_colsel]);
            unsigned B[2][2][4];
#pragma unroll
            for (int h = 0; h < 2; h++)
#pragma unroll
                for (int nt2 = 0; nt2 < 2; nt2++)
                    ldsm4(B[h][nt2],
                          &wcur[(h * 128 + b_row + nt2 * 16) * W_STRIDE +
                                s * 8 + b_ksel]);
#pragma unroll
            for (int mt = 0; mt < 2; mt++)
#pragma unroll
                for (int nt = 0; nt < 4; nt++) {
                    const unsigned* bh = &B[0][nt >> 1][(nt & 1) * 2];
                    const unsigned* bl = &B[1][nt >> 1][(nt & 1) * 2];
                    mma16816(C[mt][nt], A[0][mt], bh);
                    mma16816(C[mt][nt], A[0][mt], bl);
                    mma16816(C[mt][nt], A[1][mt], bh);
                }
        }
        __syncthreads();
        if (kc + 2 < 10) {
            prefetch_a2(ab + (kc & 1) * ABUF_ELEM, m0, kc + 2, tid);
            prefetch_w2(wb + (kc & 1) * WBUF_U32, layer, kc + 2, tid);
            asm volatile("cp.async.commit_group;\n" ::: "memory");
        }
    }

    // epilogue: bias + store
    const float* __restrict__ bias = b_sl + layer * DIM;
#pragma unroll
    for (int mt = 0; mt < 2; mt++) {
#pragma unroll
        for (int nt = 0; nt < 4; nt++) {
            int col  = n_base + nt * 8 + tig * 2;
            int row0 = m0 + m_base + mt * 16 + g;
            float b0 = bias[col], b1 = bias[col + 1];
            float2 v0 = make_float2(C[mt][nt][0] + b0, C[mt][nt][1] + b1);
            float2 v1 = make_float2(C[mt][nt][2] + b0, C[mt][nt][3] + b1);
            if (row0 < N_ENT)
                *reinterpret_cast<float2*>(&outbuf[row0 * DIM + col]) = v0;
            if (row0 + 8 < N_ENT)
                *reinterpret_cast<float2*>(&outbuf[(row0 + 8) * DIM + col]) = v1;
        }
    }
}

// ---------------- BN stats ------------------------------------------------
__global__ __launch_bounds__(256) void k_bn_stats(int outsel) {
    const float* __restrict__ outbuf = outsel ? g_out1 : g_out0;
    int tid  = threadIdx.x;
    int c4   = tid & 31;
    int rsub = tid >> 5;
    int r0   = blockIdx.x * 1024;
    float4 s = make_float4(0.f, 0.f, 0.f, 0.f);
    float4 q = make_float4(0.f, 0.f, 0.f, 0.f);
    for (int i = 0; i < 128; i++) {
        int r = r0 + rsub + i * 8;
        if (r < N_ENT) {
            float invd = 1.0f / fmaxf((float)g_hist[r], 1.0f);
            float4 v = *reinterpret_cast<const float4*>(&outbuf[r * DIM + c4 * 4]);
            v.x *= invd; v.y *= invd; v.z *= invd; v.w *= invd;
            s.x += v.x; s.y += v.y; s.z += v.z; s.w += v.w;
            q.x += v.x * v.x; q.y += v.y * v.y;
            q.z += v.z * v.z; q.w += v.w * v.w;
        }
    }
    atomicAdd(&g_sum[c4 * 4 + 0], s.x);
    atomicAdd(&g_sum[c4 * 4 + 1], s.y);
    atomicAdd(&g_sum[c4 * 4 + 2], s.z);
    atomicAdd(&g_sum[c4 * 4 + 3], s.w);
    atomicAdd(&g_sumsq[c4 * 4 + 0], q.x);
    atomicAdd(&g_sumsq[c4 * 4 + 1], q.y);
    atomicAdd(&g_sumsq[c4 * 4 + 2], q.z);
    atomicAdd(&g_sumsq[c4 * 4 + 3], q.w);
}

// ---------------- BN finalize ---------------------------------------------
__global__ void k_bn_final(int layer, const float* __restrict__ gamma,
                           const float* __restrict__ beta) {
    int c = threadIdx.x;
    if (c >= DIM) return;
    const float INV_N = 1.0f / (float)N_ENT;
    float mu  = g_sum[c] * INV_N;
    float var = g_sumsq[c] * INV_N - mu * mu;
    float rs  = rsqrtf(var + BN_EPS);
    float sc  = rs * gamma[layer * DIM + c];
    g_scale[c] = sc;
    g_shift[c] = beta[layer * DIM + c] - mu * sc;
}

// ---------------- scoring -------------------------------------------------
__global__ __launch_bounds__(256) void k_score(const int* __restrict__ head,
                                               const int* __restrict__ relidx,
                                               const int* __restrict__ tail,
                                               const int* __restrict__ neg,
                                               const float* __restrict__ rel_tab,
                                               float* __restrict__ out) {
    __shared__ float hr[DIM];
    int b = blockIdx.x;
    int tid = threadIdx.x;
    int h = head[b], r = relidx[b], t = tail[b];
    if (tid < DIM) {
        float invd = 1.0f / fmaxf((float)g_hist[h], 1.0f);
        float v = g_out1[h * DIM + tid];
        v = fmaxf(fmaf(v * invd, g_scale[tid], g_shift[tid]), 0.f);
        hr[tid] = v + rel_tab[r * DIM + tid];
    }
    __syncthreads();

    int wid = tid >> 5, lane = tid & 31;
    float4 hv = reinterpret_cast<const float4*>(hr)[lane];
    float4 sc = *reinterpret_cast<const float4*>(&g_scale[lane * 4]);
    float4 sh = *reinterpret_cast<const float4*>(&g_shift[lane * 4]);

    for (int j = wid; j < 1 + N_NEG; j += 8) {
        int target = (j == 0) ? t : neg[b * N_NEG + (j - 1)];
        float invd = 1.0f / fmaxf((float)g_hist[target], 1.0f);
        float4 ev = reinterpret_cast<const float4*>(&g_out1[target * DIM])[lane];
        ev = bnrelu4(ev, invd, sc, sh);
        float dx = hv.x - ev.x, dy = hv.y - ev.y,
              dz = hv.z - ev.z, dw = hv.w - ev.w;
        float sum = dx * dx + dy * dy + dz * dz + dw * dw;
#pragma unroll
        for (int off = 16; off > 0; off >>= 1)
            sum += __shfl_xor_sync(0xffffffffu, sum, off);
        if (lane == 0) {
            float scv = -sqrtf(sum);
            if (j == 0) out[b] = scv;
            else        out[BATCH + b * N_NEG + (j - 1)] = scv;
        }
    }
}

// ---------------- launcher ------------------------------------------------
extern "C" void kernel_launch(void* const* d_in, const int* in_sizes, int n_in,
                              void* d_out, int out_size) {
    const int*   head    = (const int*)d_in[0];
    const int*   relidx  = (const int*)d_in[1];
    const int*   tail    = (const int*)d_in[2];
    const int*   neg     = (const int*)d_in[3];
    const int*   ei      = (const int*)d_in[4];
    const int*   et      = (const int*)d_in[5];
    const float* ent_tab = (const float*)d_in[6];
    const float* rel_tab = (const float*)d_in[7];
    const float* bases   = (const float*)d_in[8];
    const float* coeffs  = (const float*)d_in[9];
    const float* w_sl    = (const float*)d_in[10];
    const float* b_sl    = (const float*)d_in[11];
    const float* gamma   = (const float*)d_in[12];
    const float* beta    = (const float*)d_in[13];
    float* out = (float*)d_out;

    cudaFuncSetAttribute(k_gemm2,
                         cudaFuncAttributeMaxDynamicSharedMemorySize, SMEM_G);

    int ggrid = (N_ENT + 127) / 128;
    int egrid = (N_ENT + 7) / 8;

    // edge sort (by dst) + weights
    k_zero_all<<<(N_ENT + 255) / 256, 256>>>();
    k_hist<<<(N_EDGES + 255) / 256, 256>>>(ei);
    k_scan_part<<<NSCANB, 256>>>();
    k_scatter<<<(N_EDGES + 255) / 256, 256>>>(ei, et);
    k_wcat<<<(2 * 128 * 320 + 255) / 256, 256>>>(w_sl, bases);

    // layer 0
    k_edge_agg<<<egrid, 256>>>(coeffs, ent_tab, 0);
    k_gemm2<<<ggrid, 512, SMEM_G>>>(0, ent_tab, b_sl, 0);
    k_zero_stats<<<1, 128>>>();
    k_bn_stats<<<(N_ENT + 1023) / 1024, 256>>>(0);
    k_bn_final<<<1, 128>>>(0, gamma, beta);

    // layer 1
    k_edge_agg<<<egrid, 256>>>(coeffs + N_REL * N_BASES, ent_tab, 1);
    k_gemm2<<<ggrid, 512, SMEM_G>>>(1, ent_tab, b_sl, 1);
    k_zero_stats<<<1, 128>>>();
    k_bn_stats<<<(N_ENT + 1023) / 1024, 256>>>(1);
    k_bn_final<<<1, 128>>>(1, gamma, beta);

    // scoring
    k_score<<<BATCH, 256>>>(head, relidx, tail, neg, rel_tab, out);
}

// round 14
// speedup vs baseline: 2.1530x; 1.1781x over previous
#include <cuda_runtime.h>
#include <cuda_bf16.h>
#include <math.h>

#define N_ENT    100000
#define N_REL    16
#define DIM      128
#define N_BASES  4
#define N_EDGES  640000
#define BATCH    1024
#define N_NEG    64
#define BN_EPS   1e-5f
#define NSCANB   391          // ceil(N_ENT/256)

// GEMM geometry: CTA = 256 thr (8 warps), tile M=64, N=128, K-chunk=64
#define A_STRIDE 72                       // bf16 per A row (144 B)
#define ABUF_ELEM (2 * 64 * A_STRIDE)     // bf16 per A buffer (hi+lo planes)
#define W_STRIDE 36                       // u32 per W row (144 B)
#define WBUF_U32 (2 * 128 * W_STRIDE)
#define SMEM_A  (2 * ABUF_ELEM * 2)       // 36864 B (double buffered)
#define SMEM_W  (2 * WBUF_U32 * 4)        // 73728 B (double buffered)
#define SMEM_G  (SMEM_A + SMEM_W)         // 110592 B -> 2 CTAs/SM

// ---------------- device scratch (static) ---------------------------------
__device__ float g_out0[N_ENT * DIM];
__device__ float g_out1[N_ENT * DIM];
__device__ __nv_bfloat16 g_aggh[N_ENT * 512];   // aggregated msgs, bf16 hi
__device__ __nv_bfloat16 g_aggl[N_ENT * 512];   // bf16 lo residual
__device__ float g_sum[DIM];
__device__ float g_sumsq[DIM];
__device__ float g_scale[DIM];
__device__ float g_shift[DIM];
// counting sort of edges by DST; g_hist doubles as deg
__device__ int g_hist[N_ENT];
__device__ int g_histL[N_ENT];
__device__ int g_bsum[NSCANB];
__device__ int g_cursor[N_ENT];
__device__ int g_total;
__device__ int g_es[N_EDGES];
__device__ int g_et[N_EDGES];
// Wfull = [w_sl ; B0..B3] (640 x 128), bf16 hi/lo u32 k-pairs,
// layout [l][n][k2]: idx = (l*128 + n)*320 + k2
__device__ unsigned g_W32h[2 * 128 * 320];
__device__ unsigned g_W32l[2 * 128 * 320];

// ---------------- setup ---------------------------------------------------
__global__ void k_zero_all() {
    int i = blockIdx.x * blockDim.x + threadIdx.x;
    if (i < N_ENT) { g_hist[i] = 0; g_cursor[i] = 0; }
    if (i < DIM) { g_sum[i] = 0.0f; g_sumsq[i] = 0.0f; }
    if (i == 0) g_total = 0;
}

__global__ void k_hist(const int* __restrict__ ei) {
    int e = blockIdx.x * blockDim.x + threadIdx.x;
    if (e < N_EDGES) atomicAdd(&g_hist[ei[N_EDGES + e]], 1);
}

// per-block scan + atomic global offset (cross-block order irrelevant)
__global__ __launch_bounds__(256) void k_scan_part() {
    __shared__ int sm[256];
    int t = threadIdx.x;
    int idx = blockIdx.x * 256 + t;
    int v = (idx < N_ENT) ? g_hist[idx] : 0;
    int x = v;
    sm[t] = x; __syncthreads();
#pragma unroll
    for (int off = 1; off < 256; off <<= 1) {
        int y = (t >= off) ? sm[t - off] : 0;
        __syncthreads();
        x += y; sm[t] = x;
        __syncthreads();
    }
    if (idx < N_ENT) g_histL[idx] = x - v;
    if (t == 255) g_bsum[blockIdx.x] = atomicAdd(&g_total, x);
}

__global__ void k_scatter(const int* __restrict__ ei,
                          const int* __restrict__ et) {
    int e = blockIdx.x * blockDim.x + threadIdx.x;
    if (e >= N_EDGES) return;
    int s = ei[e];
    int d = ei[N_EDGES + e];
    int pos = g_histL[d] + g_bsum[d >> 8] + atomicAdd(&g_cursor[d], 1);
    g_es[pos] = s; g_et[pos] = et[e];
}

// Wfull rows: k<128 -> w_sl[k][n];  k>=128 -> bases[b][kr][n]
__global__ void k_wcat(const float* __restrict__ w_sl,
                       const float* __restrict__ bases) {
    int idx = blockIdx.x * blockDim.x + threadIdx.x;
    int total = 2 * 128 * 320;
    if (idx >= total) return;
    int l   = idx / (128 * 320);
    int rem = idx - l * (128 * 320);
    int n   = rem / 320;
    int k2  = rem - n * 320;
    int k   = 2 * k2;
    float v0, v1;
    if (k < DIM) {
        v0 = w_sl[l * DIM * DIM + k * DIM + n];
        v1 = w_sl[l * DIM * DIM + (k + 1) * DIM + n];
    } else {
        int kk = k - DIM;
        int b = kk >> 7;
        int kr = kk & 127;
        const float* bp = bases + (l * N_BASES + b) * DIM * DIM;
        v0 = bp[kr * DIM + n];
        v1 = bp[(kr + 1) * DIM + n];
    }
    __nv_bfloat16 h0 = __float2bfloat16(v0);
    __nv_bfloat16 h1 = __float2bfloat16(v1);
    __nv_bfloat16 l0 = __float2bfloat16(v0 - __bfloat162float(h0));
    __nv_bfloat16 l1 = __float2bfloat16(v1 - __bfloat162float(h1));
    __nv_bfloat162 ph(h0, h1), pl(l0, l1);
    g_W32h[idx] = *reinterpret_cast<unsigned*>(&ph);
    g_W32l[idx] = *reinterpret_cast<unsigned*>(&pl);
}

// ---------------- helpers -------------------------------------------------
__device__ __forceinline__ float4 bnrelu4(float4 v, float invd,
                                          float4 sc, float4 sh) {
    v.x = fmaxf(fmaf(v.x * invd, sc.x, sh.x), 0.f);
    v.y = fmaxf(fmaf(v.y * invd, sc.y, sh.y), 0.f);
    v.z = fmaxf(fmaf(v.z * invd, sc.z, sh.z), 0.f);
    v.w = fmaxf(fmaf(v.w * invd, sc.w, sh.w), 0.f);
    return v;
}

__device__ __forceinline__ void mma16816(float* c, const unsigned* a,
                                         const unsigned* b) {
    asm volatile(
        "mma.sync.aligned.m16n8k16.row.col.f32.bf16.bf16.f32 "
        "{%0,%1,%2,%3}, {%4,%5,%6,%7}, {%8,%9}, {%0,%1,%2,%3};\n"
        : "+f"(c[0]), "+f"(c[1]), "+f"(c[2]), "+f"(c[3])
        : "r"(a[0]), "r"(a[1]), "r"(a[2]), "r"(a[3]), "r"(b[0]), "r"(b[1]));
}

__device__ __forceinline__ void ldsm4(unsigned* r, const void* p) {
    unsigned addr = (unsigned)__cvta_generic_to_shared(p);
    asm volatile(
        "ldmatrix.sync.aligned.m8n8.x4.shared.b16 {%0,%1,%2,%3}, [%4];"
        : "=r"(r[0]), "=r"(r[1]), "=r"(r[2]), "=r"(r[3]) : "r"(addr));
}

__device__ __forceinline__ void cp16(void* dst_smem, const void* src) {
    unsigned d = (unsigned)__cvta_generic_to_shared(dst_smem);
    asm volatile("cp.async.cg.shared.global [%0], [%1], 16;\n"
                 :: "r"(d), "l"(src));
}

// ---------------- edge aggregation (dst-sorted, warp per dst, MLP=2) ------
__global__ __launch_bounds__(256) void k_edge_agg(const float* __restrict__ coeff,
                                                  const float* __restrict__ xext,
                                                  int bnflag) {
    __shared__ float csm[N_REL * 4];
    int tid = threadIdx.x;
    if (tid < N_REL * 4) csm[tid] = coeff[tid];
    __syncthreads();

    int d    = blockIdx.x * 8 + (tid >> 5);
    int lane = tid & 31;
    if (d >= N_ENT) return;

    int start = g_histL[d] + g_bsum[d >> 8];
    int end   = start + g_hist[d];
    const float* __restrict__ xsrc = bnflag ? g_out0 : xext;

    float4 sc, sh;
    if (bnflag) {
        sc = *reinterpret_cast<const float4*>(&g_scale[lane * 4]);
        sh = *reinterpret_cast<const float4*>(&g_shift[lane * 4]);
    }

    float4 a0 = make_float4(0.f, 0.f, 0.f, 0.f);
    float4 a1 = a0, a2 = a0, a3 = a0;

    int e = start;
    for (; e + 1 < end; e += 2) {
        int s0 = g_es[e],     t0 = g_et[e];
        int s1 = g_es[e + 1], t1 = g_et[e + 1];
        float4 c0 = *reinterpret_cast<const float4*>(&csm[t0 * 4]);
        float4 c1 = *reinterpret_cast<const float4*>(&csm[t1 * 4]);
        float4 x0 = *reinterpret_cast<const float4*>(&xsrc[s0 * DIM + lane * 4]);
        float4 x1 = *reinterpret_cast<const float4*>(&xsrc[s1 * DIM + lane * 4]);
        if (bnflag) {
            float i0 = 1.0f / fmaxf((float)g_hist[s0], 1.0f);
            float i1 = 1.0f / fmaxf((float)g_hist[s1], 1.0f);
            x0 = bnrelu4(x0, i0, sc, sh);
            x1 = bnrelu4(x1, i1, sc, sh);
        }
        a0.x = fmaf(c0.x, x0.x, fmaf(c1.x, x1.x, a0.x));
        a0.y = fmaf(c0.x, x0.y, fmaf(c1.x, x1.y, a0.y));
        a0.z = fmaf(c0.x, x0.z, fmaf(c1.x, x1.z, a0.z));
        a0.w = fmaf(c0.x, x0.w, fmaf(c1.x, x1.w, a0.w));
        a1.x = fmaf(c0.y, x0.x, fmaf(c1.y, x1.x, a1.x));
        a1.y = fmaf(c0.y, x0.y, fmaf(c1.y, x1.y, a1.y));
        a1.z = fmaf(c0.y, x0.z, fmaf(c1.y, x1.z, a1.z));
        a1.w = fmaf(c0.y, x0.w, fmaf(c1.y, x1.w, a1.w));
        a2.x = fmaf(c0.z, x0.x, fmaf(c1.z, x1.x, a2.x));
        a2.y = fmaf(c0.z, x0.y, fmaf(c1.z, x1.y, a2.y));
        a2.z = fmaf(c0.z, x0.z, fmaf(c1.z, x1.z, a2.z));
        a2.w = fmaf(c0.z, x0.w, fmaf(c1.z, x1.w, a2.w));
        a3.x = fmaf(c0.w, x0.x, fmaf(c1.w, x1.x, a3.x));
        a3.y = fmaf(c0.w, x0.y, fmaf(c1.w, x1.y, a3.y));
        a3.z = fmaf(c0.w, x0.z, fmaf(c1.w, x1.z, a3.z));
        a3.w = fmaf(c0.w, x0.w, fmaf(c1.w, x1.w, a3.w));
    }
    if (e < end) {
        int s0 = g_es[e], t0 = g_et[e];
        float4 c0 = *reinterpret_cast<const float4*>(&csm[t0 * 4]);
        float4 x0 = *reinterpret_cast<const float4*>(&xsrc[s0 * DIM + lane * 4]);
        if (bnflag) {
            float i0 = 1.0f / fmaxf((float)g_hist[s0], 1.0f);
            x0 = bnrelu4(x0, i0, sc, sh);
        }
        a0.x = fmaf(c0.x, x0.x, a0.x); a0.y = fmaf(c0.x, x0.y, a0.y);
        a0.z = fmaf(c0.x, x0.z, a0.z); a0.w = fmaf(c0.x, x0.w, a0.w);
        a1.x = fmaf(c0.y, x0.x, a1.x); a1.y = fmaf(c0.y, x0.y, a1.y);
        a1.z = fmaf(c0.y, x0.z, a1.z); a1.w = fmaf(c0.y, x0.w, a1.w);
        a2.x = fmaf(c0.z, x0.x, a2.x); a2.y = fmaf(c0.z, x0.y, a2.y);
        a2.z = fmaf(c0.z, x0.z, a2.z); a2.w = fmaf(c0.z, x0.w, a2.w);
        a3.x = fmaf(c0.w, x0.x, a3.x); a3.y = fmaf(c0.w, x0.y, a3.y);
        a3.z = fmaf(c0.w, x0.z, a3.z); a3.w = fmaf(c0.w, x0.w, a3.w);
    }

    float4 acc[4] = {a0, a1, a2, a3};
#pragma unroll
    for (int b = 0; b < 4; b++) {
        float4 a = acc[b];
        __nv_bfloat16 hx = __float2bfloat16(a.x);
        __nv_bfloat16 hy = __float2bfloat16(a.y);
        __nv_bfloat16 hz = __float2bfloat16(a.z);
        __nv_bfloat16 hw = __float2bfloat16(a.w);
        __nv_bfloat16 lx = __float2bfloat16(a.x - __bfloat162float(hx));
        __nv_bfloat16 ly = __float2bfloat16(a.y - __bfloat162float(hy));
        __nv_bfloat16 lz = __float2bfloat16(a.z - __bfloat162float(hz));
        __nv_bfloat16 lw = __float2bfloat16(a.w - __bfloat162float(hw));
        __nv_bfloat162 hp0(hx, hy), hp1(hz, hw), lp0(lx, ly), lp1(lz, lw);
        int off = d * 512 + b * 128 + lane * 4;
        uint2 hv = make_uint2(*reinterpret_cast<unsigned*>(&hp0),
                              *reinterpret_cast<unsigned*>(&hp1));
        uint2 lv = make_uint2(*reinterpret_cast<unsigned*>(&lp0),
                              *reinterpret_cast<unsigned*>(&lp1));
        *reinterpret_cast<uint2*>(&g_aggh[off]) = hv;
        *reinterpret_cast<uint2*>(&g_aggl[off]) = lv;
    }
}

// ---------------- GEMM: out = [x | agg] @ Wfull + bias; fused BN stats ----
__device__ __forceinline__ void prefetch_w2(unsigned* wbuf, int layer,
                                            int kc, int tid) {
#pragma unroll
    for (int i = 0; i < 8; i++) {
        int lin = tid + i * 256;          // 0..2047
        int h   = lin >> 10;
        int rem = lin & 1023;
        int n   = rem >> 3;
        int q   = rem & 7;
        const unsigned* src = (h ? g_W32l : g_W32h) +
                              (layer * 128 + n) * 320 + kc * 32 + q * 4;
        cp16(&wbuf[(h * 128 + n) * W_STRIDE + q * 4], src);
    }
}

__device__ __forceinline__ void prefetch_a2(__nv_bfloat16* abuf, int m0,
                                            int kc, int tid) {
    int aggc = kc * 64 - 128;             // kc >= 2 always
#pragma unroll
    for (int i = 0; i < 4; i++) {
        int lin = tid + i * 256;          // 0..1023
        int h   = lin >> 9;
        int rem = lin & 511;
        int row = rem >> 3;
        int q   = rem & 7;
        int r = m0 + row; if (r >= N_ENT) r = N_ENT - 1;
        const __nv_bfloat16* src = (h ? g_aggl : g_aggh) +
                                   r * 512 + aggc + q * 8;
        cp16(&abuf[(h * 64 + row) * A_STRIDE + q * 8], src);
    }
}

__global__ __launch_bounds__(256, 2) void k_gemm2(int layer,
                                                  const float* __restrict__ xext,
                                                  const float* __restrict__ b_sl,
                                                  int bnflag) {
    extern __shared__ unsigned char smraw[];
    __nv_bfloat16* ab = reinterpret_cast<__nv_bfloat16*>(smraw);
    unsigned* wb = reinterpret_cast<unsigned*>(smraw + SMEM_A);

    const float* __restrict__ xsrc = bnflag ? g_out0 : xext;
    float* __restrict__ outbuf = bnflag ? g_out1 : g_out0;

    int tid  = threadIdx.x;
    int lane = tid & 31;
    int wid  = tid >> 5;
    int g    = lane >> 2;
    int tig  = lane & 3;
    int m_base = (wid & 1) * 32;
    int n_base = (wid >> 1) * 32;
    int m0 = blockIdx.x * 64;

    // prefetch W chunks 0,1
    prefetch_w2(wb, layer, 0, tid);
    asm volatile("cp.async.commit_group;\n" ::: "memory");
    prefetch_w2(wb + WBUF_U32, layer, 1, tid);
    asm volatile("cp.async.commit_group;\n" ::: "memory");

    // x part (K 0..127) -> A buffers 0,1; BN+ReLU opt; split hi/lo
#pragma unroll
    for (int i = 0; i < 8; i++) {
        int lin = tid + i * 256;          // 0..2047 float4
        int row = lin >> 5;               // 0..63
        int q   = lin & 31;
        int c0  = q * 4;
        float4 v = make_float4(0.f, 0.f, 0.f, 0.f);
        if (m0 + row < N_ENT) {
            v = *reinterpret_cast<const float4*>(&xsrc[(m0 + row) * DIM + c0]);
            if (bnflag) {
                float invd = 1.0f / fmaxf((float)g_hist[m0 + row], 1.0f);
                float4 sc = *reinterpret_cast<const float4*>(&g_scale[c0]);
                float4 sh = *reinterpret_cast<const float4*>(&g_shift[c0]);
                v = bnrelu4(v, invd, sc, sh);
            }
        }
        __nv_bfloat16 h0 = __float2bfloat16(v.x);
        __nv_bfloat16 h1 = __float2bfloat16(v.y);
        __nv_bfloat16 h2 = __float2bfloat16(v.z);
        __nv_bfloat16 h3 = __float2bfloat16(v.w);
        __nv_bfloat16 l0 = __float2bfloat16(v.x - __bfloat162float(h0));
        __nv_bfloat16 l1 = __float2bfloat16(v.y - __bfloat162float(h1));
        __nv_bfloat16 l2 = __float2bfloat16(v.z - __bfloat162float(h2));
        __nv_bfloat16 l3 = __float2bfloat16(v.w - __bfloat162float(h3));
        int buf = c0 >> 6;
        int kl  = c0 & 63;
        __nv_bfloat16* dsth = ab + buf * ABUF_ELEM + row * A_STRIDE + kl;
        __nv_bfloat16* dstl = dsth + 64 * A_STRIDE;
        *reinterpret_cast<__nv_bfloat162*>(dsth)     = __nv_bfloat162(h0, h1);
        *reinterpret_cast<__nv_bfloat162*>(dsth + 2) = __nv_bfloat162(h2, h3);
        *reinterpret_cast<__nv_bfloat162*>(dstl)     = __nv_bfloat162(l0, l1);
        *reinterpret_cast<__nv_bfloat162*>(dstl + 2) = __nv_bfloat162(l2, l3);
    }

    int a_row = m_base + (lane & 15);
    int a_colsel = (lane >> 4) << 3;
    int b_row = n_base + (lane & 7) + ((lane & 16) ? 8 : 0);
    int b_ksel = (lane & 8) ? 4 : 0;

    float C[2][4][4];
#pragma unroll
    for (int mt = 0; mt < 2; mt++)
#pragma unroll
        for (int nt = 0; nt < 4; nt++)
#pragma unroll
            for (int j = 0; j < 4; j++) C[mt][nt][j] = 0.0f;

    for (int kc = 0; kc < 10; kc++) {
        if (kc < 9)
            asm volatile("cp.async.wait_group 1;\n" ::: "memory");
        else
            asm volatile("cp.async.wait_group 0;\n" ::: "memory");
        __syncthreads();

        __nv_bfloat16* acur = ab + (kc & 1) * ABUF_ELEM;
        unsigned* wcur = wb + (kc & 1) * WBUF_U32;

#pragma unroll
        for (int s = 0; s < 4; s++) {
            unsigned A[2][2][4];
#pragma unroll
            for (int h = 0; h < 2; h++)
#pragma unroll
                for (int mt = 0; mt < 2; mt++)
                    ldsm4(A[h][mt],
                          &acur[(h * 64 + a_row + mt * 16) * A_STRIDE +
                                s * 16 + a_colsel]);
            unsigned B[2][2][4];
#pragma unroll
            for (int h = 0; h < 2; h++)
#pragma unroll
                for (int nt2 = 0; nt2 < 2; nt2++)
                    ldsm4(B[h][nt2],
                          &wcur[(h * 128 + b_row + nt2 * 16) * W_STRIDE +
                                s * 8 + b_ksel]);
#pragma unroll
            for (int mt = 0; mt < 2; mt++)
#pragma unroll
                for (int nt = 0; nt < 4; nt++) {
                    const unsigned* bh = &B[0][nt >> 1][(nt & 1) * 2];
                    const unsigned* bl = &B[1][nt >> 1][(nt & 1) * 2];
                    mma16816(C[mt][nt], A[0][mt], bh);
                    mma16816(C[mt][nt], A[0][mt], bl);
                    mma16816(C[mt][nt], A[1][mt], bh);
                }
        }
        __syncthreads();
        if (kc + 2 < 10) {
            prefetch_a2(ab + (kc & 1) * ABUF_ELEM, m0, kc + 2, tid);
            prefetch_w2(wb + (kc & 1) * WBUF_U32, layer, kc + 2, tid);
            asm volatile("cp.async.commit_group;\n" ::: "memory");
        }
    }

    // stats scratch aliased onto dead A buffer (all reads done, synced)
    float* ssum = reinterpret_cast<float*>(ab);
    float* ssq  = ssum + 128;
    if (tid < 128) { ssum[tid] = 0.0f; ssq[tid] = 0.0f; }
    __syncthreads();

    // per-thread row weights (same rows for every nt)
    float invd_[2][2];
#pragma unroll
    for (int mt = 0; mt < 2; mt++)
#pragma unroll
        for (int j = 0; j < 2; j++) {
            int r = m0 + m_base + mt * 16 + g + j * 8;
            invd_[mt][j] = (r < N_ENT) ? 1.0f / fmaxf((float)g_hist[r], 1.0f)
                                       : 0.0f;
        }

    const float* __restrict__ bias = b_sl + layer * DIM;
#pragma unroll
    for (int nt = 0; nt < 4; nt++) {
        int col = n_base + nt * 8 + tig * 2;
        float b0 = bias[col], b1 = bias[col + 1];
        float cs0 = 0.f, cq0 = 0.f, cs1 = 0.f, cq1 = 0.f;
#pragma unroll
        for (int mt = 0; mt < 2; mt++) {
            int row0 = m0 + m_base + mt * 16 + g;
            float2 v0 = make_float2(C[mt][nt][0] + b0, C[mt][nt][1] + b1);
            float2 v1 = make_float2(C[mt][nt][2] + b0, C[mt][nt][3] + b1);
            if (row0 < N_ENT)
                *reinterpret_cast<float2*>(&outbuf[row0 * DIM + col]) = v0;
            if (row0 + 8 < N_ENT)
                *reinterpret_cast<float2*>(&outbuf[(row0 + 8) * DIM + col]) = v1;
            float w;
            w = v0.x * invd_[mt][0]; cs0 += w; cq0 += w * w;
            w = v0.y * invd_[mt][0]; cs1 += w; cq1 += w * w;
            w = v1.x * invd_[mt][1]; cs0 += w; cq0 += w * w;
            w = v1.y * invd_[mt][1]; cs1 += w; cq1 += w * w;
        }
        atomicAdd(&ssum[col], cs0);
        atomicAdd(&ssq[col], cq0);
        atomicAdd(&ssum[col + 1], cs1);
        atomicAdd(&ssq[col + 1], cq1);
    }
    __syncthreads();
    if (tid < 128) {
        atomicAdd(&g_sum[tid], ssum[tid]);
        atomicAdd(&g_sumsq[tid], ssq[tid]);
    }
}

// ---------------- BN finalize (also resets accumulators) ------------------
__global__ void k_bn_final(int layer, const float* __restrict__ gamma,
                           const float* __restrict__ beta) {
    int c = threadIdx.x;
    if (c >= DIM) return;
    const float INV_N = 1.0f / (float)N_ENT;
    float mu  = g_sum[c] * INV_N;
    float var = g_sumsq[c] * INV_N - mu * mu;
    float rs  = rsqrtf(var + BN_EPS);
    float sc  = rs * gamma[layer * DIM + c];
    g_scale[c] = sc;
    g_shift[c] = beta[layer * DIM + c] - mu * sc;
    g_sum[c] = 0.0f;           // ready for next layer
    g_sumsq[c] = 0.0f;
}

// ---------------- scoring -------------------------------------------------
__global__ __launch_bounds__(256) void k_score(const int* __restrict__ head,
                                               const int* __restrict__ relidx,
                                               const int* __restrict__ tail,
                                               const int* __restrict__ neg,
                                               const float* __restrict__ rel_tab,
                                               float* __restrict__ out) {
    __shared__ float hr[DIM];
    int b = blockIdx.x;
    int tid = threadIdx.x;
    int h = head[b], r = relidx[b], t = tail[b];
    if (tid < DIM) {
        float invd = 1.0f / fmaxf((float)g_hist[h], 1.0f);
        float v = g_out1[h * DIM + tid];
        v = fmaxf(fmaf(v * invd, g_scale[tid], g_shift[tid]), 0.f);
        hr[tid] = v + rel_tab[r * DIM + tid];
    }
    __syncthreads();

    int wid = tid >> 5, lane = tid & 31;
    float4 hv = reinterpret_cast<const float4*>(hr)[lane];
    float4 sc = *reinterpret_cast<const float4*>(&g_scale[lane * 4]);
    float4 sh = *reinterpret_cast<const float4*>(&g_shift[lane * 4]);

    for (int j = wid; j < 1 + N_NEG; j += 8) {
        int target = (j == 0) ? t : neg[b * N_NEG + (j - 1)];
        float invd = 1.0f / fmaxf((float)g_hist[target], 1.0f);
        float4 ev = reinterpret_cast<const float4*>(&g_out1[target * DIM])[lane];
        ev = bnrelu4(ev, invd, sc, sh);
        float dx = hv.x - ev.x, dy = hv.y - ev.y,
              dz = hv.z - ev.z, dw = hv.w - ev.w;
        float sum = dx * dx + dy * dy + dz * dz + dw * dw;
#pragma unroll
        for (int off = 16; off > 0; off >>= 1)
            sum += __shfl_xor_sync(0xffffffffu, sum, off);
        if (lane == 0) {
            float scv = -sqrtf(sum);
            if (j == 0) out[b] = scv;
            else        out[BATCH + b * N_NEG + (j - 1)] = scv;
        }
    }
}

// ---------------- launcher ------------------------------------------------
extern "C" void kernel_launch(void* const* d_in, const int* in_sizes, int n_in,
                              void* d_out, int out_size) {
    const int*   head    = (const int*)d_in[0];
    const int*   relidx  = (const int*)d_in[1];
    const int*   tail    = (const int*)d_in[2];
    const int*   neg     = (const int*)d_in[3];
    const int*   ei      = (const int*)d_in[4];
    const int*   et      = (const int*)d_in[5];
    const float* ent_tab = (const float*)d_in[6];
    const float* rel_tab = (const float*)d_in[7];
    const float* bases   = (const float*)d_in[8];
    const float* coeffs  = (const float*)d_in[9];
    const float* w_sl    = (const float*)d_in[10];
    const float* b_sl    = (const float*)d_in[11];
    const float* gamma   = (const float*)d_in[12];
    const float* beta    = (const float*)d_in[13];
    float* out = (float*)d_out;

    cudaFuncSetAttribute(k_gemm2,
                         cudaFuncAttributeMaxDynamicSharedMemorySize, SMEM_G);

    int ggrid = (N_ENT + 63) / 64;
    int egrid = (N_ENT + 7) / 8;

    // sort-by-dst + weights
    k_zero_all<<<(N_ENT + 255) / 256, 256>>>();
    k_hist<<<(N_EDGES + 255) / 256, 256>>>(ei);
    k_scan_part<<<NSCANB, 256>>>();
    k_scatter<<<(N_EDGES + 255) / 256, 256>>>(ei, et);
    k_wcat<<<(2 * 128 * 320 + 255) / 256, 256>>>(w_sl, bases);

    // layer 0
    k_edge_agg<<<egrid, 256>>>(coeffs, ent_tab, 0);
    k_gemm2<<<ggrid, 256, SMEM_G>>>(0, ent_tab, b_sl, 0);
    k_bn_final<<<1, 128>>>(0, gamma, beta);

    // layer 1
    k_edge_agg<<<egrid, 256>>>(coeffs + N_REL * N_BASES, ent_tab, 1);
    k_gemm2<<<ggrid, 256, SMEM_G>>>(1, ent_tab, b_sl, 1);
    k_bn_final<<<1, 128>>>(1, gamma, beta);

    // scoring
    k_score<<<BATCH, 256>>>(head, relidx, tail, neg, rel_tab, out);
}